// round 2
// baseline (speedup 1.0000x reference)
#include <cuda_runtime.h>

// Problem dims (fixed by the reference)
constexpr int Bb  = 2;
constexpr int SQn = 2048;
constexpr int SKn = 2048;
constexpr int Dn  = 1024;
constexpr int Hn  = 16;
constexpr int HDn = 64;

constexpr int Mn = Bb * SQn;   // 4096 rows for all GEMMs
constexpr int Nn = 1024;       // H*HD == D
constexpr int Kn = 1024;       // D

// Scratch (static device globals; no dynamic allocation allowed)
__device__ float g_q [Bb * Hn * SQn * HDn];   // [B,H,SQ,HD]
__device__ float g_k [Bb * Hn * SKn * HDn];   // [B,H,SK,HD]
__device__ float g_v [Bb * Hn * SKn * HDn];   // [B,H,SK,HD]
__device__ float g_ao[Bb * SQn * Dn];         // [B,SQ,D] (heads concatenated)

// ---------------------------------------------------------------------------
// Tiled SGEMM: C = A[4096,1024] * W + bias
// MODE 0: W is per-head [H, D, HD] (addr = h*D*HD + k*HD + e, col n = h*HD+e),
//         output scattered to [B,H,S,HD].
// MODE 1: W row-major [K, N], output row-major [M, N].
// BM=BN=128, BK=8, 256 threads, 8x8 per-thread tile.
// ---------------------------------------------------------------------------
template <int MODE>
__global__ __launch_bounds__(256) void sgemm_kernel(
    const float* __restrict__ A, const float* __restrict__ W,
    const float* __restrict__ bias, float* __restrict__ C)
{
    constexpr int BM = 128, BN = 128, BK = 8;

    __shared__ float As[BK][BM + 4];   // +4 pad: conflict-free transposed stores
    __shared__ float Bs[BK][BN];

    const int tid = threadIdx.x;
    const int tx = tid & 15;           // 0..15 -> N direction
    const int ty = tid >> 4;           // 0..15 -> M direction
    const int m0 = blockIdx.y * BM;
    const int n0 = blockIdx.x * BN;

    // Global load indexing
    const int arow = tid >> 1;          // 0..127
    const int acol = (tid & 1) * 4;     // 0 or 4
    const int bk   = tid >> 5;          // 0..7 (one K-row per warp)
    const int bn   = (tid & 31) * 4;    // 0..124

    const float* Aptr = A + (long)(m0 + arow) * Kn + acol;

    float acc[8][8];
#pragma unroll
    for (int i = 0; i < 8; i++)
#pragma unroll
        for (int j = 0; j < 8; j++) acc[i][j] = 0.f;

    for (int kt = 0; kt < Kn; kt += BK) {
        // global -> regs
        float4 av = *(const float4*)(Aptr + kt);
        float4 bv;
        if (MODE == 0) {
            const int n = n0 + bn;
            const int hh = n >> 6;          // n / HD
            const int e  = n & 63;          // n % HD
            bv = *(const float4*)(W + ((long)hh * Dn + (kt + bk)) * HDn + e);
        } else {
            bv = *(const float4*)(W + (long)(kt + bk) * Nn + n0 + bn);
        }

        __syncthreads();
        // regs -> smem (A transposed)
        As[acol + 0][arow] = av.x;
        As[acol + 1][arow] = av.y;
        As[acol + 2][arow] = av.z;
        As[acol + 3][arow] = av.w;
        *(float4*)&Bs[bk][bn] = bv;
        __syncthreads();

#pragma unroll
        for (int kk = 0; kk < BK; kk++) {
            float a[8], b[8];
            *(float4*)(a + 0) = *(const float4*)&As[kk][ty * 8 + 0];
            *(float4*)(a + 4) = *(const float4*)&As[kk][ty * 8 + 4];
            *(float4*)(b + 0) = *(const float4*)&Bs[kk][tx * 8 + 0];
            *(float4*)(b + 4) = *(const float4*)&Bs[kk][tx * 8 + 4];
#pragma unroll
            for (int i = 0; i < 8; i++)
#pragma unroll
                for (int j = 0; j < 8; j++)
                    acc[i][j] += a[i] * b[j];
        }
    }

    // Epilogue: add bias, scatter per MODE, float4 stores
#pragma unroll
    for (int i = 0; i < 8; i++) {
        const int m = m0 + ty * 8 + i;
#pragma unroll
        for (int jj = 0; jj < 2; jj++) {
            const int n = n0 + tx * 8 + jj * 4;
            float4 r;
            r.x = acc[i][jj * 4 + 0] + bias[n + 0];
            r.y = acc[i][jj * 4 + 1] + bias[n + 1];
            r.z = acc[i][jj * 4 + 2] + bias[n + 2];
            r.w = acc[i][jj * 4 + 3] + bias[n + 3];
            if (MODE == 0) {
                const int b  = m >> 11;      // m / SQ
                const int s  = m & 2047;     // m % SQ
                const int hh = n >> 6;
                const int e  = n & 63;
                float* cp = C + (((long)(b * Hn + hh) * SQn + s) * HDn + e);
                *(float4*)cp = r;
            } else {
                *(float4*)(C + (long)m * Nn + n) = r;
            }
        }
    }
}

// ---------------------------------------------------------------------------
// Flash attention: one thread per query row, 128 rows per block.
// q row (64 f32) and output accumulator (64 f32) in registers.
// K/V tiles of 64 keys in smem; all smem reads are warp-broadcast float4
// (1 LDS.128 per 4 FFMA). Online softmax in chunks of 16 keys,
// unconditional rescale (no divergence). No cross-thread reductions.
// Output written concat-head: [B, SQ, H*HD].
// ---------------------------------------------------------------------------
__global__ __launch_bounds__(128) void flash_kernel(
    const float* __restrict__ q, const float* __restrict__ k,
    const float* __restrict__ v, float* __restrict__ out)
{
    const int s   = blockIdx.x * 128 + threadIdx.x;  // query row
    const int h   = blockIdx.y;
    const int b   = blockIdx.z;

    const float* qp = q + ((long)(b * Hn + h) * SQn + s) * HDn;
    const float* kp = k + ((long)(b * Hn + h) * SKn) * HDn;
    const float* vp = v + ((long)(b * Hn + h) * SKn) * HDn;

    float qr[HDn];
#pragma unroll
    for (int i = 0; i < HDn / 4; i++) {
        float4 t = ((const float4*)qp)[i];
        qr[4 * i + 0] = t.x; qr[4 * i + 1] = t.y;
        qr[4 * i + 2] = t.z; qr[4 * i + 3] = t.w;
    }

    __shared__ float4 Ks[64][HDn / 4];
    __shared__ float4 Vs[64][HDn / 4];

    float o[HDn];
#pragma unroll
    for (int e = 0; e < HDn; e++) o[e] = 0.f;
    float m = -3.0e38f;
    float l = 0.f;
    const float scale = 0.125f;   // 1/sqrt(64)

    for (int t0 = 0; t0 < SKn; t0 += 64) {
        __syncthreads();
        // 64 rows x 16 float4 = 1024 float4; 128 threads -> 8 each (coalesced)
#pragma unroll
        for (int i = 0; i < 8; i++) {
            const int idx = threadIdx.x + i * 128;
            const int r = idx >> 4, c = idx & 15;
            Ks[r][c] = ((const float4*)(kp + (long)(t0 + r) * HDn))[c];
            Vs[r][c] = ((const float4*)(vp + (long)(t0 + r) * HDn))[c];
        }
        __syncthreads();

#pragma unroll
        for (int jc = 0; jc < 4; jc++) {
            float sc[16];
#pragma unroll
            for (int j = 0; j < 16; j++) sc[j] = 0.f;

            // S = q . K^T  (broadcast LDS.128, 4 FFMA per load)
#pragma unroll
            for (int d4 = 0; d4 < HDn / 4; d4++) {
                const float qx = qr[4 * d4 + 0], qy = qr[4 * d4 + 1];
                const float qz = qr[4 * d4 + 2], qw = qr[4 * d4 + 3];
#pragma unroll
                for (int j = 0; j < 16; j++) {
                    float4 kv = Ks[jc * 16 + j][d4];
                    sc[j] += qx * kv.x + qy * kv.y;
                    sc[j] += qz * kv.z + qw * kv.w;
                }
            }

            float mt = m;
#pragma unroll
            for (int j = 0; j < 16; j++) {
                sc[j] *= scale;
                mt = fmaxf(mt, sc[j]);
            }
            // unconditional rescale (exp(0)=1 when no new max)
            const float f = __expf(m - mt);
            m = mt;
            l *= f;
#pragma unroll
            for (int e = 0; e < HDn; e++) o[e] *= f;

#pragma unroll
            for (int j = 0; j < 16; j++) {
                const float p = __expf(sc[j] - m);
                l += p;
                sc[j] = p;
            }

            // O += P . V  (broadcast LDS.128, 4 FFMA per load)
#pragma unroll
            for (int j = 0; j < 16; j++) {
                const float p = sc[j];
#pragma unroll
                for (int e4 = 0; e4 < HDn / 4; e4++) {
                    float4 vv = Vs[jc * 16 + j][e4];
                    o[4 * e4 + 0] += p * vv.x;
                    o[4 * e4 + 1] += p * vv.y;
                    o[4 * e4 + 2] += p * vv.z;
                    o[4 * e4 + 3] += p * vv.w;
                }
            }
        }
    }

    const float inv = 1.f / l;
    float* op = out + (long)(b * SQn + s) * Dn + h * HDn;
#pragma unroll
    for (int e4 = 0; e4 < HDn / 4; e4++) {
        float4 r;
        r.x = o[4 * e4 + 0] * inv;
        r.y = o[4 * e4 + 1] * inv;
        r.z = o[4 * e4 + 2] * inv;
        r.w = o[4 * e4 + 3] * inv;
        ((float4*)op)[e4] = r;
    }
}

// ---------------------------------------------------------------------------
extern "C" void kernel_launch(void* const* d_in, const int* in_sizes, int n_in,
                              void* d_out, int out_size)
{
    const float* x   = (const float*)d_in[0];
    const float* enc = (const float*)d_in[1];
    const float* Wq  = (const float*)d_in[2];
    const float* bq  = (const float*)d_in[3];
    const float* Wk  = (const float*)d_in[4];
    const float* bk  = (const float*)d_in[5];
    const float* Wv  = (const float*)d_in[6];
    const float* bv  = (const float*)d_in[7];
    const float* Wo  = (const float*)d_in[8];
    const float* bo  = (const float*)d_in[9];
    float* out = (float*)d_out;

    float *qp, *kp, *vp, *aop;
    cudaGetSymbolAddress((void**)&qp,  g_q);
    cudaGetSymbolAddress((void**)&kp,  g_k);
    cudaGetSymbolAddress((void**)&vp,  g_v);
    cudaGetSymbolAddress((void**)&aop, g_ao);

    dim3 ggrid(Nn / 128, Mn / 128);   // (8, 32)

    sgemm_kernel<0><<<ggrid, 256>>>(x,   Wq, bq, qp);
    sgemm_kernel<0><<<ggrid, 256>>>(enc, Wk, bk, kp);
    sgemm_kernel<0><<<ggrid, 256>>>(enc, Wv, bv, vp);

    flash_kernel<<<dim3(SQn / 128, Hn, Bb), 128>>>(qp, kp, vp, aop);

    sgemm_kernel<1><<<ggrid, 256>>>(aop, Wo, bo, out);
}

// round 4
// speedup vs baseline: 2.4647x; 2.4647x over previous
#include <cuda_runtime.h>

// Problem dims (fixed by the reference)
constexpr int Bb  = 2;
constexpr int SQn = 2048;
constexpr int SKn = 2048;
constexpr int Dn  = 1024;
constexpr int Hn  = 16;
constexpr int HDn = 64;

constexpr int Mn = Bb * SQn;   // 4096 rows for all GEMMs
constexpr int Nn = 1024;       // H*HD == D
constexpr int Kn = 1024;       // D

// Scratch (static device globals; no dynamic allocation allowed)
__device__ float g_q [Bb * Hn * SQn * HDn];   // [B,H,SQ,HD]
__device__ float g_k [Bb * Hn * SKn * HDn];   // [B,H,SK,HD]
__device__ float g_v [Bb * Hn * SKn * HDn];   // [B,H,SK,HD]
__device__ float g_ao[Bb * SQn * Dn];         // [B,SQ,D] (heads concatenated)

// ---------------------------------------------------------------------------
// Tiled SGEMM: C = A[4096,1024] * W + bias   (double-buffered smem)
// MODE 0: W per-head [H, D, HD], output scattered to [B,H,S,HD].
// MODE 1: W row-major [K, N], output row-major [M, N].
// BM=BN=128, BK=8, 256 threads, 8x8 per-thread tile.
// ---------------------------------------------------------------------------
template <int MODE>
__global__ __launch_bounds__(256) void sgemm_kernel(
    const float* __restrict__ A, const float* __restrict__ W,
    const float* __restrict__ bias, float* __restrict__ C)
{
    constexpr int BM = 128, BN = 128, BK = 8;

    __shared__ float As[2][BK][BM + 4];
    __shared__ float Bs[2][BK][BN];

    const int tid = threadIdx.x;
    const int tx = tid & 15;           // N direction
    const int ty = tid >> 4;           // M direction
    const int m0 = blockIdx.y * BM;
    const int n0 = blockIdx.x * BN;

    const int arow = tid >> 1;          // 0..127
    const int acol = (tid & 1) * 4;     // 0 or 4
    const int bk   = tid >> 5;          // 0..7
    const int bn   = (tid & 31) * 4;    // 0..124

    const float* Aptr = A + (long)(m0 + arow) * Kn + acol;

    float acc[8][8];
#pragma unroll
    for (int i = 0; i < 8; i++)
#pragma unroll
        for (int j = 0; j < 8; j++) acc[i][j] = 0.f;

    // helper lambda for B address
    auto loadB = [&](int kt) -> float4 {
        if (MODE == 0) {
            const int n = n0 + bn;
            const int hh = n >> 6;
            const int e  = n & 63;
            return *(const float4*)(W + ((long)hh * Dn + (kt + bk)) * HDn + e);
        } else {
            return *(const float4*)(W + (long)(kt + bk) * Nn + n0 + bn);
        }
    };

    // prologue: fill buffer 0
    {
        float4 av = *(const float4*)(Aptr + 0);
        float4 bv = loadB(0);
        As[0][acol + 0][arow] = av.x;
        As[0][acol + 1][arow] = av.y;
        As[0][acol + 2][arow] = av.z;
        As[0][acol + 3][arow] = av.w;
        *(float4*)&Bs[0][bk][bn] = bv;
    }
    __syncthreads();

    int buf = 0;
    for (int kt = 0; kt < Kn; kt += BK) {
        float4 av2, bv2;
        const bool more = (kt + BK) < Kn;
        if (more) {
            av2 = *(const float4*)(Aptr + kt + BK);
            bv2 = loadB(kt + BK);
        }

#pragma unroll
        for (int kk = 0; kk < BK; kk++) {
            float a[8], b[8];
            *(float4*)(a + 0) = *(const float4*)&As[buf][kk][ty * 8 + 0];
            *(float4*)(a + 4) = *(const float4*)&As[buf][kk][ty * 8 + 4];
            *(float4*)(b + 0) = *(const float4*)&Bs[buf][kk][tx * 8 + 0];
            *(float4*)(b + 4) = *(const float4*)&Bs[buf][kk][tx * 8 + 4];
#pragma unroll
            for (int i = 0; i < 8; i++)
#pragma unroll
                for (int j = 0; j < 8; j++)
                    acc[i][j] += a[i] * b[j];
        }

        if (more) {
            const int nb = buf ^ 1;
            As[nb][acol + 0][arow] = av2.x;
            As[nb][acol + 1][arow] = av2.y;
            As[nb][acol + 2][arow] = av2.z;
            As[nb][acol + 3][arow] = av2.w;
            *(float4*)&Bs[nb][bk][bn] = bv2;
        }
        __syncthreads();
        buf ^= 1;
    }

#pragma unroll
    for (int i = 0; i < 8; i++) {
        const int m = m0 + ty * 8 + i;
#pragma unroll
        for (int jj = 0; jj < 2; jj++) {
            const int n = n0 + tx * 8 + jj * 4;
            float4 r;
            r.x = acc[i][jj * 4 + 0] + bias[n + 0];
            r.y = acc[i][jj * 4 + 1] + bias[n + 1];
            r.z = acc[i][jj * 4 + 2] + bias[n + 2];
            r.w = acc[i][jj * 4 + 3] + bias[n + 3];
            if (MODE == 0) {
                const int b  = m >> 11;
                const int s  = m & 2047;
                const int hh = n >> 6;
                const int e  = n & 63;
                float* cp = C + (((long)(b * Hn + hh) * SQn + s) * HDn + e);
                *(float4*)cp = r;
            } else {
                *(float4*)(C + (long)m * Nn + n) = r;
            }
        }
    }
}

// ---------------------------------------------------------------------------
// Flash attention v2: GEMM-style tiling.
// Block = 64 query rows; key tiles of 64. 128 threads = 16(ty:rows) x 8(tx).
// Thread owns S tile 4 rows x 8 keys (keys interleaved: tx+8j) and
// O tile 4 rows x 8 dims (dims interleaved: float4 chunks tx and tx+8).
// Q (pre-scaled), K, V, P all staged in dynamic smem; every inner-loop LDS is
// bank-conflict-free. Row softmax reductions: 3x shfl_xor over 8 lanes.
// ---------------------------------------------------------------------------
constexpr int FL_SMEM =
    3 * 64 * 17 * 16      /* Qs, Ks, Vs: [64][17] float4 */
    + 64 * 65 * 4;        /* Ps: [64][65] float          */

__global__ __launch_bounds__(128) void flash_kernel(
    const float* __restrict__ q, const float* __restrict__ k,
    const float* __restrict__ v, float* __restrict__ out)
{
    extern __shared__ char smem_raw[];
    float4* Qs = (float4*)smem_raw;                       // [64][17]
    float4* Ks = (float4*)(smem_raw + 17408);             // [64][17]
    float4* Vs = (float4*)(smem_raw + 34816);             // [64][17]
    float*  Ps = (float*) (smem_raw + 52224);             // [64][65]

    const int tid = threadIdx.x;
    const int tx  = tid & 7;     // key/dim group
    const int ty  = tid >> 3;    // row group (0..15), rows 4*ty..4*ty+3
    const int r0  = blockIdx.x * 64;
    const int h   = blockIdx.y;
    const int b   = blockIdx.z;

    const float* qg = q + ((long)(b * Hn + h) * SQn + r0) * HDn;
    const float* kg = k + ((long)(b * Hn + h) * SKn) * HDn;
    const float* vg = v + ((long)(b * Hn + h) * SKn) * HDn;

    // Load Q tile, folding in the 1/sqrt(HD) scale.
#pragma unroll
    for (int i = 0; i < 8; i++) {
        const int idx = tid + i * 128;           // 0..1023
        const int rr = idx >> 4, cc = idx & 15;
        float4 t = ((const float4*)(qg + (long)rr * HDn))[cc];
        t.x *= 0.125f; t.y *= 0.125f; t.z *= 0.125f; t.w *= 0.125f;
        Qs[rr * 17 + cc] = t;
    }

    float o[4][8];
#pragma unroll
    for (int i = 0; i < 4; i++)
#pragma unroll
        for (int d = 0; d < 8; d++) o[i][d] = 0.f;
    float m[4] = {-3.0e38f, -3.0e38f, -3.0e38f, -3.0e38f};
    float l[4] = {0.f, 0.f, 0.f, 0.f};

    for (int t0 = 0; t0 < SKn; t0 += 64) {
        __syncthreads();   // prev PV done with Vs/Ps; (iter 0: Qs ready)
#pragma unroll
        for (int i = 0; i < 8; i++) {
            const int idx = tid + i * 128;
            const int rr = idx >> 4, cc = idx & 15;
            Ks[rr * 17 + cc] = ((const float4*)(kg + (long)(t0 + rr) * HDn))[cc];
            Vs[rr * 17 + cc] = ((const float4*)(vg + (long)(t0 + rr) * HDn))[cc];
        }
        __syncthreads();

        // S = Q . K^T  (thread: 4 rows x 8 keys, keys = tx + 8j)
        float sc[4][8];
#pragma unroll
        for (int i = 0; i < 4; i++)
#pragma unroll
            for (int j = 0; j < 8; j++) sc[i][j] = 0.f;

#pragma unroll
        for (int d4 = 0; d4 < 16; d4++) {
            float4 a0 = Qs[(4 * ty + 0) * 17 + d4];
            float4 a1 = Qs[(4 * ty + 1) * 17 + d4];
            float4 a2 = Qs[(4 * ty + 2) * 17 + d4];
            float4 a3 = Qs[(4 * ty + 3) * 17 + d4];
#pragma unroll
            for (int j = 0; j < 8; j++) {
                float4 kb = Ks[(tx + 8 * j) * 17 + d4];
                sc[0][j] += a0.x * kb.x + a0.y * kb.y + a0.z * kb.z + a0.w * kb.w;
                sc[1][j] += a1.x * kb.x + a1.y * kb.y + a1.z * kb.z + a1.w * kb.w;
                sc[2][j] += a2.x * kb.x + a2.y * kb.y + a2.z * kb.z + a2.w * kb.w;
                sc[3][j] += a3.x * kb.x + a3.y * kb.y + a3.z * kb.z + a3.w * kb.w;
            }
        }

        // Online softmax per row (8 lanes share a row; redundant but in-sync)
        float fresc[4];
#pragma unroll
        for (int i = 0; i < 4; i++) {
            float pm = sc[i][0];
#pragma unroll
            for (int j = 1; j < 8; j++) pm = fmaxf(pm, sc[i][j]);
            pm = fmaxf(pm, __shfl_xor_sync(0xFFFFFFFFu, pm, 1));
            pm = fmaxf(pm, __shfl_xor_sync(0xFFFFFFFFu, pm, 2));
            pm = fmaxf(pm, __shfl_xor_sync(0xFFFFFFFFu, pm, 4));
            const float mnew = fmaxf(m[i], pm);
            const float f = __expf(m[i] - mnew);
            m[i] = mnew;
            float psum = 0.f;
#pragma unroll
            for (int j = 0; j < 8; j++) {
                const float p = __expf(sc[i][j] - mnew);
                psum += p;
                Ps[(4 * ty + i) * 65 + (tx + 8 * j)] = p;
            }
            psum += __shfl_xor_sync(0xFFFFFFFFu, psum, 1);
            psum += __shfl_xor_sync(0xFFFFFFFFu, psum, 2);
            psum += __shfl_xor_sync(0xFFFFFFFFu, psum, 4);
            l[i] = l[i] * f + psum;
            fresc[i] = f;
        }
#pragma unroll
        for (int i = 0; i < 4; i++)
#pragma unroll
            for (int d = 0; d < 8; d++) o[i][d] *= fresc[i];

        __syncthreads();   // Ps visible to all lanes

        // O += P . V  (thread: 4 rows x dims {4tx..4tx+3, 32+4tx..32+4tx+3})
#pragma unroll
        for (int kk = 0; kk < 64; kk++) {
            const float a0 = Ps[(4 * ty + 0) * 65 + kk];
            const float a1 = Ps[(4 * ty + 1) * 65 + kk];
            const float a2 = Ps[(4 * ty + 2) * 65 + kk];
            const float a3 = Ps[(4 * ty + 3) * 65 + kk];
            const float4 v0 = Vs[kk * 17 + tx];
            const float4 v1 = Vs[kk * 17 + tx + 8];
            o[0][0] += a0 * v0.x; o[0][1] += a0 * v0.y; o[0][2] += a0 * v0.z; o[0][3] += a0 * v0.w;
            o[0][4] += a0 * v1.x; o[0][5] += a0 * v1.y; o[0][6] += a0 * v1.z; o[0][7] += a0 * v1.w;
            o[1][0] += a1 * v0.x; o[1][1] += a1 * v0.y; o[1][2] += a1 * v0.z; o[1][3] += a1 * v0.w;
            o[1][4] += a1 * v1.x; o[1][5] += a1 * v1.y; o[1][6] += a1 * v1.z; o[1][7] += a1 * v1.w;
            o[2][0] += a2 * v0.x; o[2][1] += a2 * v0.y; o[2][2] += a2 * v0.z; o[2][3] += a2 * v0.w;
            o[2][4] += a2 * v1.x; o[2][5] += a2 * v1.y; o[2][6] += a2 * v1.z; o[2][7] += a2 * v1.w;
            o[3][0] += a3 * v0.x; o[3][1] += a3 * v0.y; o[3][2] += a3 * v0.z; o[3][3] += a3 * v0.w;
            o[3][4] += a3 * v1.x; o[3][5] += a3 * v1.y; o[3][6] += a3 * v1.z; o[3][7] += a3 * v1.w;
        }
    }

    // Epilogue: normalize and store (concat-head layout [B,SQ,H*HD])
#pragma unroll
    for (int i = 0; i < 4; i++) {
        const float inv = 1.f / l[i];
        const int row = r0 + 4 * ty + i;
        float* op = out + ((long)(b * SQn + row)) * Dn + h * HDn;
        float4 w0, w1;
        w0.x = o[i][0] * inv; w0.y = o[i][1] * inv; w0.z = o[i][2] * inv; w0.w = o[i][3] * inv;
        w1.x = o[i][4] * inv; w1.y = o[i][5] * inv; w1.z = o[i][6] * inv; w1.w = o[i][7] * inv;
        *(float4*)(op + 4 * tx)      = w0;
        *(float4*)(op + 32 + 4 * tx) = w1;
    }
}

// ---------------------------------------------------------------------------
extern "C" void kernel_launch(void* const* d_in, const int* in_sizes, int n_in,
                              void* d_out, int out_size)
{
    const float* x   = (const float*)d_in[0];
    const float* enc = (const float*)d_in[1];
    const float* Wq  = (const float*)d_in[2];
    const float* bq  = (const float*)d_in[3];
    const float* Wk  = (const float*)d_in[4];
    const float* bk  = (const float*)d_in[5];
    const float* Wv  = (const float*)d_in[6];
    const float* bv  = (const float*)d_in[7];
    const float* Wo  = (const float*)d_in[8];
    const float* bo  = (const float*)d_in[9];
    float* out = (float*)d_out;

    float *qp, *kp, *vp, *aop;
    cudaGetSymbolAddress((void**)&qp,  g_q);
    cudaGetSymbolAddress((void**)&kp,  g_k);
    cudaGetSymbolAddress((void**)&vp,  g_v);
    cudaGetSymbolAddress((void**)&aop, g_ao);

    cudaFuncSetAttribute(flash_kernel,
                         cudaFuncAttributeMaxDynamicSharedMemorySize, FL_SMEM);

    dim3 ggrid(Nn / 128, Mn / 128);   // (8, 32)

    sgemm_kernel<0><<<ggrid, 256>>>(x,   Wq, bq, qp);
    sgemm_kernel<0><<<ggrid, 256>>>(enc, Wk, bk, kp);
    sgemm_kernel<0><<<ggrid, 256>>>(enc, Wv, bv, vp);

    flash_kernel<<<dim3(SQn / 64, Hn, Bb), 128, FL_SMEM>>>(qp, kp, vp, aop);

    sgemm_kernel<1><<<ggrid, 256>>>(aop, Wo, bo, out);
}

// round 8
// speedup vs baseline: 3.1873x; 1.2932x over previous
#include <cuda_runtime.h>

typedef unsigned long long u64;

// Problem dims (fixed by the reference)
constexpr int Bb  = 2;
constexpr int SQn = 2048;
constexpr int SKn = 2048;
constexpr int Dn  = 1024;
constexpr int Hn  = 16;
constexpr int HDn = 64;

constexpr int Mn = Bb * SQn;   // 4096 rows for all GEMMs
constexpr int Nn = 1024;       // H*HD == D
constexpr int Kn = 1024;       // D

// Scratch (static device globals; no dynamic allocation allowed)
__device__ float g_q [Bb * Hn * SQn * HDn];   // [B,H,SQ,HD]
__device__ float g_k [Bb * Hn * SKn * HDn];   // [B,H,SK,HD]
__device__ float g_v [Bb * Hn * SKn * HDn];   // [B,H,SK,HD]
__device__ float g_ao[Bb * SQn * Dn];         // [B,SQ,D] (heads concatenated)

// ---- packed fp32x2 helpers (Blackwell FFMA2 path; full fp32 precision) ----
__device__ __forceinline__ u64 fma2(u64 a, u64 b, u64 c) {
    u64 d;
    asm("fma.rn.f32x2 %0, %1, %2, %3;" : "=l"(d) : "l"(a), "l"(b), "l"(c));
    return d;
}
__device__ __forceinline__ u64 mul2(u64 a, u64 b) {
    u64 d;
    asm("mul.rn.f32x2 %0, %1, %2;" : "=l"(d) : "l"(a), "l"(b));
    return d;
}
__device__ __forceinline__ u64 pack_dup(float a) {
    u64 d;
    unsigned u = __float_as_uint(a);
    asm("mov.b64 %0, {%1, %1};" : "=l"(d) : "r"(u));
    return d;
}
__device__ __forceinline__ float2 unpack2(u64 d) {
    unsigned lo, hi;
    asm("mov.b64 {%0, %1}, %2;" : "=r"(lo), "=r"(hi) : "l"(d));
    return make_float2(__uint_as_float(lo), __uint_as_float(hi));
}

// ---------------------------------------------------------------------------
// Tiled SGEMM: C = A[4096,1024] * W + bias   (double-buffered smem, FFMA2)
// MODE 0: W per-head [H, D, HD], output scattered to [B,H,S,HD].
// MODE 1: W row-major [K, N], output row-major [M, N].
// BM=BN=128, BK=8, 256 threads, 8x8 per-thread tile (acc packed along N).
// ---------------------------------------------------------------------------
template <int MODE>
__global__ __launch_bounds__(256) void sgemm_kernel(
    const float* __restrict__ A, const float* __restrict__ W,
    const float* __restrict__ bias, float* __restrict__ C)
{
    constexpr int BM = 128, BN = 128, BK = 8;

    __shared__ float As[2][BK][BM + 4];
    __shared__ float Bs[2][BK][BN];

    const int tid = threadIdx.x;
    const int tx = tid & 15;           // N direction
    const int ty = tid >> 4;           // M direction
    const int m0 = blockIdx.y * BM;
    const int n0 = blockIdx.x * BN;

    const int arow = tid >> 1;          // 0..127
    const int acol = (tid & 1) * 4;     // 0 or 4
    const int bk   = tid >> 5;          // 0..7
    const int bn   = (tid & 31) * 4;    // 0..124

    const float* Aptr = A + (long)(m0 + arow) * Kn + acol;

    // hoisted B pointer: advances by a fixed stride each K-tile
    const float* Bptr;
    long bstride;
    if (MODE == 0) {
        const int n  = n0 + bn;
        const int hh = n >> 6;
        const int e  = n & 63;
        Bptr = W + ((long)hh * Dn + bk) * HDn + e;
        bstride = (long)BK * HDn;
    } else {
        Bptr = W + (long)bk * Nn + n0 + bn;
        bstride = (long)BK * Nn;
    }

    u64 acc2[8][4];
#pragma unroll
    for (int i = 0; i < 8; i++)
#pragma unroll
        for (int jp = 0; jp < 4; jp++) acc2[i][jp] = 0ull;

    // prologue: fill buffer 0
    {
        float4 av = *(const float4*)(Aptr);
        float4 bv = *(const float4*)(Bptr);
        As[0][acol + 0][arow] = av.x;
        As[0][acol + 1][arow] = av.y;
        As[0][acol + 2][arow] = av.z;
        As[0][acol + 3][arow] = av.w;
        *(float4*)&Bs[0][bk][bn] = bv;
    }
    __syncthreads();

    int buf = 0;
    for (int kt = 0; kt < Kn; kt += BK) {
        float4 av2, bv2;
        const bool more = (kt + BK) < Kn;
        if (more) {
            av2 = *(const float4*)(Aptr + kt + BK);
            bv2 = *(const float4*)(Bptr + ((kt / BK) + 1) * bstride);
        }

#pragma unroll
        for (int kk = 0; kk < BK; kk++) {
            float a[8];
            *(float4*)(a + 0) = *(const float4*)&As[buf][kk][ty * 8 + 0];
            *(float4*)(a + 4) = *(const float4*)&As[buf][kk][ty * 8 + 4];
            const ulonglong2 bp0 = *(const ulonglong2*)&Bs[buf][kk][tx * 8 + 0];
            const ulonglong2 bp1 = *(const ulonglong2*)&Bs[buf][kk][tx * 8 + 4];
            const u64 b2[4] = {bp0.x, bp0.y, bp1.x, bp1.y};
#pragma unroll
            for (int i = 0; i < 8; i++) {
                const u64 ai = pack_dup(a[i]);
#pragma unroll
                for (int jp = 0; jp < 4; jp++)
                    acc2[i][jp] = fma2(ai, b2[jp], acc2[i][jp]);
            }
        }

        if (more) {
            const int nb = buf ^ 1;
            As[nb][acol + 0][arow] = av2.x;
            As[nb][acol + 1][arow] = av2.y;
            As[nb][acol + 2][arow] = av2.z;
            As[nb][acol + 3][arow] = av2.w;
            *(float4*)&Bs[nb][bk][bn] = bv2;
        }
        __syncthreads();
        buf ^= 1;
    }

#pragma unroll
    for (int i = 0; i < 8; i++) {
        const int m = m0 + ty * 8 + i;
        float c[8];
#pragma unroll
        for (int jp = 0; jp < 4; jp++) {
            float2 t = unpack2(acc2[i][jp]);
            c[2 * jp + 0] = t.x;
            c[2 * jp + 1] = t.y;
        }
#pragma unroll
        for (int jj = 0; jj < 2; jj++) {
            const int n = n0 + tx * 8 + jj * 4;
            float4 r;
            r.x = c[jj * 4 + 0] + bias[n + 0];
            r.y = c[jj * 4 + 1] + bias[n + 1];
            r.z = c[jj * 4 + 2] + bias[n + 2];
            r.w = c[jj * 4 + 3] + bias[n + 3];
            if (MODE == 0) {
                const int b  = m >> 11;
                const int s  = m & 2047;
                const int hh = n >> 6;
                const int e  = n & 63;
                float* cp = C + (((long)(b * Hn + hh) * SQn + s) * HDn + e);
                *(float4*)cp = r;
            } else {
                *(float4*)(C + (long)m * Nn + n) = r;
            }
        }
    }
}

// ---------------------------------------------------------------------------
// Flash attention v3: GEMM-style tiling with FFMA2.
// Block = 64 query rows; key tiles of 64. 128 threads = 16(ty) x 8(tx).
// QK packs along head-dim (both operand pairs free from float4 loads,
// horizontal add at tile end). PV packs along output dims (V pairs free,
// P broadcast-dup'd). All inner-loop LDS bank-conflict-free.
// ---------------------------------------------------------------------------
constexpr int FL_SMEM =
    3 * 64 * 17 * 16      /* Qs, Ks, Vs: [64][17] float4 */
    + 64 * 65 * 4;        /* Ps: [64][65] float          */

__global__ __launch_bounds__(128) void flash_kernel(
    const float* __restrict__ q, const float* __restrict__ k,
    const float* __restrict__ v, float* __restrict__ out)
{
    extern __shared__ char smem_raw[];
    float4* Qs = (float4*)smem_raw;                       // [64][17]
    float4* Ks = (float4*)(smem_raw + 17408);             // [64][17]
    float4* Vs = (float4*)(smem_raw + 34816);             // [64][17]
    float*  Ps = (float*) (smem_raw + 52224);             // [64][65]

    const int tid = threadIdx.x;
    const int tx  = tid & 7;     // key/dim group
    const int ty  = tid >> 3;    // row group (0..15), rows 4*ty..4*ty+3
    const int r0  = blockIdx.x * 64;
    const int h   = blockIdx.y;
    const int b   = blockIdx.z;

    const float* qg = q + ((long)(b * Hn + h) * SQn + r0) * HDn;
    const float* kg = k + ((long)(b * Hn + h) * SKn) * HDn;
    const float* vg = v + ((long)(b * Hn + h) * SKn) * HDn;

    // Load Q tile, folding in the 1/sqrt(HD) scale.
#pragma unroll
    for (int i = 0; i < 8; i++) {
        const int idx = tid + i * 128;           // 0..1023
        const int rr = idx >> 4, cc = idx & 15;
        float4 t = ((const float4*)(qg + (long)rr * HDn))[cc];
        t.x *= 0.125f; t.y *= 0.125f; t.z *= 0.125f; t.w *= 0.125f;
        Qs[rr * 17 + cc] = t;
    }

    u64 o2[4][4];   // rows x dim-pairs: {4tx,4tx+1},{4tx+2,4tx+3},{32+4tx,..},{32+4tx+2,..}
#pragma unroll
    for (int i = 0; i < 4; i++)
#pragma unroll
        for (int jp = 0; jp < 4; jp++) o2[i][jp] = 0ull;
    float m[4] = {-3.0e38f, -3.0e38f, -3.0e38f, -3.0e38f};
    float l[4] = {0.f, 0.f, 0.f, 0.f};

    for (int t0 = 0; t0 < SKn; t0 += 64) {
        __syncthreads();   // prev PV done with Vs/Ps; (iter 0: Qs ready)
#pragma unroll
        for (int i = 0; i < 8; i++) {
            const int idx = tid + i * 128;
            const int rr = idx >> 4, cc = idx & 15;
            Ks[rr * 17 + cc] = ((const float4*)(kg + (long)(t0 + rr) * HDn))[cc];
            Vs[rr * 17 + cc] = ((const float4*)(vg + (long)(t0 + rr) * HDn))[cc];
        }
        __syncthreads();

        // S = Q . K^T, packed along head-dim (2-wide SIMD partial sums)
        u64 sc2[4][8];
#pragma unroll
        for (int i = 0; i < 4; i++)
#pragma unroll
            for (int j = 0; j < 8; j++) sc2[i][j] = 0ull;

#pragma unroll
        for (int d4 = 0; d4 < 16; d4++) {
            const ulonglong2 a0 = *(const ulonglong2*)&Qs[(4 * ty + 0) * 17 + d4];
            const ulonglong2 a1 = *(const ulonglong2*)&Qs[(4 * ty + 1) * 17 + d4];
            const ulonglong2 a2 = *(const ulonglong2*)&Qs[(4 * ty + 2) * 17 + d4];
            const ulonglong2 a3 = *(const ulonglong2*)&Qs[(4 * ty + 3) * 17 + d4];
#pragma unroll
            for (int j = 0; j < 8; j++) {
                const ulonglong2 kb = *(const ulonglong2*)&Ks[(tx + 8 * j) * 17 + d4];
                sc2[0][j] = fma2(a0.x, kb.x, sc2[0][j]);
                sc2[0][j] = fma2(a0.y, kb.y, sc2[0][j]);
                sc2[1][j] = fma2(a1.x, kb.x, sc2[1][j]);
                sc2[1][j] = fma2(a1.y, kb.y, sc2[1][j]);
                sc2[2][j] = fma2(a2.x, kb.x, sc2[2][j]);
                sc2[2][j] = fma2(a2.y, kb.y, sc2[2][j]);
                sc2[3][j] = fma2(a3.x, kb.x, sc2[3][j]);
                sc2[3][j] = fma2(a3.y, kb.y, sc2[3][j]);
            }
        }

        // horizontal reduce packed partials
        float sc[4][8];
#pragma unroll
        for (int i = 0; i < 4; i++)
#pragma unroll
            for (int j = 0; j < 8; j++) {
                const float2 t = unpack2(sc2[i][j]);
                sc[i][j] = t.x + t.y;
            }

        // Online softmax per row (8 lanes share a row; redundant but in-sync)
        float fresc[4];
#pragma unroll
        for (int i = 0; i < 4; i++) {
            float pm = sc[i][0];
#pragma unroll
            for (int j = 1; j < 8; j++) pm = fmaxf(pm, sc[i][j]);
            pm = fmaxf(pm, __shfl_xor_sync(0xFFFFFFFFu, pm, 1));
            pm = fmaxf(pm, __shfl_xor_sync(0xFFFFFFFFu, pm, 2));
            pm = fmaxf(pm, __shfl_xor_sync(0xFFFFFFFFu, pm, 4));
            const float mnew = fmaxf(m[i], pm);
            const float f = __expf(m[i] - mnew);
            m[i] = mnew;
            float psum = 0.f;
#pragma unroll
            for (int j = 0; j < 8; j++) {
                const float p = __expf(sc[i][j] - mnew);
                psum += p;
                Ps[(4 * ty + i) * 65 + (tx + 8 * j)] = p;
            }
            psum += __shfl_xor_sync(0xFFFFFFFFu, psum, 1);
            psum += __shfl_xor_sync(0xFFFFFFFFu, psum, 2);
            psum += __shfl_xor_sync(0xFFFFFFFFu, psum, 4);
            l[i] = l[i] * f + psum;
            fresc[i] = f;
        }
#pragma unroll
        for (int i = 0; i < 4; i++) {
            const u64 f2 = pack_dup(fresc[i]);
#pragma unroll
            for (int jp = 0; jp < 4; jp++) o2[i][jp] = mul2(o2[i][jp], f2);
        }

        __syncthreads();   // Ps visible to all lanes

        // O += P . V, packed along output dims
#pragma unroll
        for (int kk = 0; kk < 64; kk++) {
            const u64 p0 = pack_dup(Ps[(4 * ty + 0) * 65 + kk]);
            const u64 p1 = pack_dup(Ps[(4 * ty + 1) * 65 + kk]);
            const u64 p2 = pack_dup(Ps[(4 * ty + 2) * 65 + kk]);
            const u64 p3 = pack_dup(Ps[(4 * ty + 3) * 65 + kk]);
            const ulonglong2 v0 = *(const ulonglong2*)&Vs[kk * 17 + tx];
            const ulonglong2 v1 = *(const ulonglong2*)&Vs[kk * 17 + tx + 8];
            o2[0][0] = fma2(p0, v0.x, o2[0][0]);
            o2[0][1] = fma2(p0, v0.y, o2[0][1]);
            o2[0][2] = fma2(p0, v1.x, o2[0][2]);
            o2[0][3] = fma2(p0, v1.y, o2[0][3]);
            o2[1][0] = fma2(p1, v0.x, o2[1][0]);
            o2[1][1] = fma2(p1, v0.y, o2[1][1]);
            o2[1][2] = fma2(p1, v1.x, o2[1][2]);
            o2[1][3] = fma2(p1, v1.y, o2[1][3]);
            o2[2][0] = fma2(p2, v0.x, o2[2][0]);
            o2[2][1] = fma2(p2, v0.y, o2[2][1]);
            o2[2][2] = fma2(p2, v1.x, o2[2][2]);
            o2[2][3] = fma2(p2, v1.y, o2[2][3]);
            o2[3][0] = fma2(p3, v0.x, o2[3][0]);
            o2[3][1] = fma2(p3, v0.y, o2[3][1]);
            o2[3][2] = fma2(p3, v1.x, o2[3][2]);
            o2[3][3] = fma2(p3, v1.y, o2[3][3]);
        }
    }

    // Epilogue: normalize and store (concat-head layout [B,SQ,H*HD])
#pragma unroll
    for (int i = 0; i < 4; i++) {
        const float inv = 1.f / l[i];
        const int row = r0 + 4 * ty + i;
        float* op = out + ((long)(b * SQn + row)) * Dn + h * HDn;
        const float2 t0 = unpack2(o2[i][0]);
        const float2 t1 = unpack2(o2[i][1]);
        const float2 t2 = unpack2(o2[i][2]);
        const float2 t3 = unpack2(o2[i][3]);
        float4 w0, w1;
        w0.x = t0.x * inv; w0.y = t0.y * inv; w0.z = t1.x * inv; w0.w = t1.y * inv;
        w1.x = t2.x * inv; w1.y = t2.y * inv; w1.z = t3.x * inv; w1.w = t3.y * inv;
        *(float4*)(op + 4 * tx)      = w0;
        *(float4*)(op + 32 + 4 * tx) = w1;
    }
}

// ---------------------------------------------------------------------------
extern "C" void kernel_launch(void* const* d_in, const int* in_sizes, int n_in,
                              void* d_out, int out_size)
{
    const float* x   = (const float*)d_in[0];
    const float* enc = (const float*)d_in[1];
    const float* Wq  = (const float*)d_in[2];
    const float* bq  = (const float*)d_in[3];
    const float* Wk  = (const float*)d_in[4];
    const float* bk  = (const float*)d_in[5];
    const float* Wv  = (const float*)d_in[6];
    const float* bv  = (const float*)d_in[7];
    const float* Wo  = (const float*)d_in[8];
    const float* bo  = (const float*)d_in[9];
    float* out = (float*)d_out;

    float *qp, *kp, *vp, *aop;
    cudaGetSymbolAddress((void**)&qp,  g_q);
    cudaGetSymbolAddress((void**)&kp,  g_k);
    cudaGetSymbolAddress((void**)&vp,  g_v);
    cudaGetSymbolAddress((void**)&aop, g_ao);

    cudaFuncSetAttribute(flash_kernel,
                         cudaFuncAttributeMaxDynamicSharedMemorySize, FL_SMEM);

    dim3 ggrid(Nn / 128, Mn / 128);   // (8, 32)

    sgemm_kernel<0><<<ggrid, 256>>>(x,   Wq, bq, qp);
    sgemm_kernel<0><<<ggrid, 256>>>(enc, Wk, bk, kp);
    sgemm_kernel<0><<<ggrid, 256>>>(enc, Wv, bv, vp);

    flash_kernel<<<dim3(SQn / 64, Hn, Bb), 128, FL_SMEM>>>(qp, kp, vp, aop);

    sgemm_kernel<1><<<ggrid, 256>>>(aop, Wo, bo, out);
}

// round 11
// speedup vs baseline: 4.5467x; 1.4265x over previous
#include <cuda_runtime.h>
#include <cuda_bf16.h>

typedef unsigned long long u64;
typedef unsigned int u32;

// Problem dims (fixed by the reference)
constexpr int Bb  = 2;
constexpr int SQn = 2048;
constexpr int SKn = 2048;
constexpr int Dn  = 1024;
constexpr int Hn  = 16;
constexpr int HDn = 64;

constexpr int Mn = Bb * SQn;   // 4096
constexpr int Nn = 1024;
constexpr int Kn = 1024;

// Scratch (static device globals; no dynamic allocation allowed)
__device__ float g_q [Mn * Dn];               // [B,SQ,H*HD] row-major
__device__ float g_k [Bb * SKn * Dn];         // [B,SK,H*HD]
__device__ float g_v [Bb * SKn * Dn];         // [B,SK,H*HD]
__device__ float g_ao[Mn * Dn];               // [B,SQ,D]
__device__ __nv_bfloat16 g_wh[4][Nn * Kn];    // transposed weights, hi
__device__ __nv_bfloat16 g_wl[4][Nn * Kn];    // transposed weights, lo
__device__ __nv_bfloat16 g_ah[3][Mn * Dn];    // activations hi: x, enc, ao
__device__ __nv_bfloat16 g_al[3][Mn * Dn];    // activations lo

// ============================ PTX helpers ===================================
__device__ __forceinline__ u32 smem_u32(const void* p) {
    u32 a;
    asm("{ .reg .u64 t; cvta.to.shared.u64 t, %1; cvt.u32.u64 %0, t; }"
        : "=r"(a) : "l"(p));
    return a;
}
__device__ __forceinline__ void ldsm4(u32* r, u32 addr) {
    asm volatile("ldmatrix.sync.aligned.m8n8.x4.shared.b16 {%0,%1,%2,%3}, [%4];"
                 : "=r"(r[0]), "=r"(r[1]), "=r"(r[2]), "=r"(r[3]) : "r"(addr));
}
__device__ __forceinline__ void mma_bf16(float* d, const u32* a, u32 b0, u32 b1) {
    asm volatile("mma.sync.aligned.m16n8k16.row.col.f32.bf16.bf16.f32 "
                 "{%0,%1,%2,%3}, {%4,%5,%6,%7}, {%8,%9}, {%0,%1,%2,%3};"
                 : "+f"(d[0]), "+f"(d[1]), "+f"(d[2]), "+f"(d[3])
                 : "r"(a[0]), "r"(a[1]), "r"(a[2]), "r"(a[3]), "r"(b0), "r"(b1));
}
__device__ __forceinline__ void cpa16(u32 saddr, const void* g) {
    asm volatile("cp.async.cg.shared.global [%0], [%1], 16;"
                 :: "r"(saddr), "l"(g) : "memory");
}

// ---- packed fp32x2 helpers (flash stays on the FFMA2 path) ----
__device__ __forceinline__ u64 fma2(u64 a, u64 b, u64 c) {
    u64 d;
    asm("fma.rn.f32x2 %0, %1, %2, %3;" : "=l"(d) : "l"(a), "l"(b), "l"(c));
    return d;
}
__device__ __forceinline__ u64 mul2(u64 a, u64 b) {
    u64 d;
    asm("mul.rn.f32x2 %0, %1, %2;" : "=l"(d) : "l"(a), "l"(b));
    return d;
}
__device__ __forceinline__ u64 pack_dup(float a) {
    u64 d;
    unsigned u = __float_as_uint(a);
    asm("mov.b64 %0, {%1, %1};" : "=l"(d) : "r"(u));
    return d;
}
__device__ __forceinline__ float2 unpack2(u64 d) {
    unsigned lo, hi;
    asm("mov.b64 {%0, %1}, %2;" : "=r"(lo), "=r"(hi) : "l"(d));
    return make_float2(__uint_as_float(lo), __uint_as_float(hi));
}

// ---------------------------------------------------------------------------
// Weight pre-pass: transpose to Wt[n][k] and split fp32 -> bf16 hi + lo.
// MODE 0: W [H, D, HD] -> n = h*64+e (blockIdx.y = h)
// MODE 1: W [K, N]     -> n = n0+e   (blockIdx.y = n0/64)
// ---------------------------------------------------------------------------
template <int MODE>
__global__ __launch_bounds__(256) void wsplit_kernel(
    const float* __restrict__ W, __nv_bfloat16* __restrict__ Th,
    __nv_bfloat16* __restrict__ Tl)
{
    __shared__ float tile[64][65];
    const int k0 = blockIdx.x * 64;
    const int by = blockIdx.y;
    const int tid = threadIdx.x;
#pragma unroll
    for (int i = 0; i < 16; i++) {
        const int idx = tid + i * 256;
        const int kk = idx >> 6, e = idx & 63;
        long off;
        if (MODE == 0) off = (long)by * 65536 + (long)(k0 + kk) * 64 + e;
        else           off = (long)(k0 + kk) * Nn + by * 64 + e;
        tile[kk][e] = W[off];
    }
    __syncthreads();
#pragma unroll
    for (int i = 0; i < 16; i++) {
        const int idx = tid + i * 256;
        const int e = idx >> 6, kk = idx & 63;
        const float v = tile[kk][e];
        const __nv_bfloat16 h = __float2bfloat16(v);
        const __nv_bfloat16 l = __float2bfloat16(v - __bfloat162float(h));
        const long o = (long)(by * 64 + e) * Kn + k0 + kk;
        Th[o] = h;
        Tl[o] = l;
    }
}

// ---------------------------------------------------------------------------
// Activation split: fp32 -> bf16 hi + lo (elementwise, float4-wide).
// grid 4096 x 256 threads x 4 elements = Mn*Dn exactly.
// ---------------------------------------------------------------------------
__global__ __launch_bounds__(256) void asplit_kernel(
    const float* __restrict__ in, __nv_bfloat16* __restrict__ h,
    __nv_bfloat16* __restrict__ l)
{
    const long i = ((long)blockIdx.x * 256 + threadIdx.x) * 4;
    const float4 t = *(const float4*)(in + i);
    const __nv_bfloat16 hx = __float2bfloat16(t.x);
    const __nv_bfloat16 hy = __float2bfloat16(t.y);
    const __nv_bfloat16 hz = __float2bfloat16(t.z);
    const __nv_bfloat16 hw = __float2bfloat16(t.w);
    const __nv_bfloat16 lx = __float2bfloat16(t.x - __bfloat162float(hx));
    const __nv_bfloat16 ly = __float2bfloat16(t.y - __bfloat162float(hy));
    const __nv_bfloat16 lz = __float2bfloat16(t.z - __bfloat162float(hz));
    const __nv_bfloat16 lw = __float2bfloat16(t.w - __bfloat162float(hw));
    uint2 hp, lp;
    hp.x = ((u32)__bfloat16_as_ushort(hy) << 16) | __bfloat16_as_ushort(hx);
    hp.y = ((u32)__bfloat16_as_ushort(hw) << 16) | __bfloat16_as_ushort(hz);
    lp.x = ((u32)__bfloat16_as_ushort(ly) << 16) | __bfloat16_as_ushort(lx);
    lp.y = ((u32)__bfloat16_as_ushort(lw) << 16) | __bfloat16_as_ushort(lz);
    *(uint2*)(h + i) = hp;
    *(uint2*)(l + i) = lp;
}

// ---------------------------------------------------------------------------
// Tensor-core split-bf16 GEMM via mma.sync (HMMA):
//   C[4096,1024] = A * Wt^T + bias,  A/Wt pre-split bf16 hi/lo [*,K] row-major.
// 128x128 tile, BK=64, cp.async double-buffered smem (SW128 swizzle),
// 8 warps (4m x 2n), warp tile 32x64 = 2x8 m16n8k16 atoms, 3 products.
// ---------------------------------------------------------------------------
constexpr int GM_SMEM = 132096;   // 2 x 64KB buffers + 1KB align slack

__global__ __launch_bounds__(256) void tc_gemm(
    const __nv_bfloat16* __restrict__ Ah, const __nv_bfloat16* __restrict__ Al,
    const __nv_bfloat16* __restrict__ Bh, const __nv_bfloat16* __restrict__ Bl,
    const float* __restrict__ bias, float* __restrict__ C)
{
    extern __shared__ char sm[];
    const u32 sbase = smem_u32(sm);
    const u32 abase = (sbase + 1023) & ~1023u;
    const int tid = threadIdx.x;
    const int m0 = blockIdx.y * 128, n0 = blockIdx.x * 128;

    const __nv_bfloat16* srcs[4] = {
        Ah + (long)m0 * Kn, Al + (long)m0 * Kn,
        Bh + (long)n0 * Kn, Bl + (long)n0 * Kn };

    // per-thread staging coords (16B quads; 4 per tile, 4 tiles)
    auto stage = [&](int c, int b) {
        const u32 dst = abase + b * 65536;
#pragma unroll
        for (int tile = 0; tile < 4; tile++) {
            const __nv_bfloat16* src = srcs[tile] + c * 64;
#pragma unroll
            for (int i = 0; i < 4; i++) {
                const int q = tid + i * 256;
                const int row = q >> 3, qd = q & 7;
                cpa16(dst + tile * 16384 + row * 128 + ((qd * 16) ^ ((row & 7) << 4)),
                      src + (long)row * Kn + qd * 8);
            }
        }
    };

    const int lane = tid & 31, wid = tid >> 5;
    const int wm = wid >> 1, wn = wid & 1;
    const int Rr = wm * 32, Ncol = wn * 64;
    const int lrow = (lane & 7) + ((lane >> 3) & 1) * 8;   // ldmatrix row-in-block
    const int lkb  = (lane >> 4) * 16;                     // k-half byte offset
    const int xorm = (lrow & 7) << 4;                      // SW128 xor (row-const)

    float acc[2][8][4];
#pragma unroll
    for (int mb = 0; mb < 2; mb++)
#pragma unroll
        for (int nb = 0; nb < 8; nb++)
#pragma unroll
            for (int r = 0; r < 4; r++) acc[mb][nb][r] = 0.f;

    stage(0, 0);
    asm volatile("cp.async.commit_group;" ::: "memory");

    for (int c = 0; c < 16; c++) {
        if (c < 15) {
            stage(c + 1, (c + 1) & 1);
            asm volatile("cp.async.commit_group;" ::: "memory");
            asm volatile("cp.async.wait_group 1;" ::: "memory");
        } else {
            asm volatile("cp.async.wait_group 0;" ::: "memory");
        }
        __syncthreads();

        const u32 sb = abase + (c & 1) * 65536;
        const u32 arow0 = sb + (Rr + lrow) * 128;
        const u32 brow0 = sb + 32768 + (Ncol + lrow) * 128;
#pragma unroll
        for (int t = 0; t < 4; t++) {
            const u32 cb = (u32)((32 * t + lkb) ^ xorm);
            u32 ah[2][4], al[2][4];
#pragma unroll
            for (int mb = 0; mb < 2; mb++) {
                ldsm4(ah[mb], arow0 + mb * 2048 + cb);
                ldsm4(al[mb], arow0 + 16384 + mb * 2048 + cb);
            }
#pragma unroll
            for (int g = 0; g < 4; g++) {
                u32 bh[4], bl[4];
                ldsm4(bh, brow0 + g * 2048 + cb);
                ldsm4(bl, brow0 + 16384 + g * 2048 + cb);
#pragma unroll
                for (int mb = 0; mb < 2; mb++) {
                    mma_bf16(acc[mb][2 * g],     ah[mb], bh[0], bh[2]);
                    mma_bf16(acc[mb][2 * g],     ah[mb], bl[0], bl[2]);
                    mma_bf16(acc[mb][2 * g],     al[mb], bh[0], bh[2]);
                    mma_bf16(acc[mb][2 * g + 1], ah[mb], bh[1], bh[3]);
                    mma_bf16(acc[mb][2 * g + 1], ah[mb], bl[1], bl[3]);
                    mma_bf16(acc[mb][2 * g + 1], al[mb], bh[1], bh[3]);
                }
            }
        }
        __syncthreads();
    }

    // Epilogue: add bias, direct float2 stores
#pragma unroll
    for (int mb = 0; mb < 2; mb++) {
        const int row = m0 + Rr + 16 * mb + (lane >> 2);
#pragma unroll
        for (int nb = 0; nb < 8; nb++) {
            const int col = n0 + Ncol + nb * 8 + (lane & 3) * 2;
            const float2 bb = *(const float2*)(bias + col);
            float2 w0, w1;
            w0.x = acc[mb][nb][0] + bb.x; w0.y = acc[mb][nb][1] + bb.y;
            w1.x = acc[mb][nb][2] + bb.x; w1.y = acc[mb][nb][3] + bb.y;
            *(float2*)(C + (long)row * Nn + col)       = w0;
            *(float2*)(C + (long)(row + 8) * Nn + col) = w1;
        }
    }
}

// ---------------------------------------------------------------------------
// Flash attention (FFMA2), q/k/v row-major [B, S, H*HD] (row stride Dn).
// ---------------------------------------------------------------------------
constexpr int FL_SMEM =
    3 * 64 * 17 * 16      /* Qs, Ks, Vs: [64][17] float4 */
    + 64 * 65 * 4;        /* Ps: [64][65] float          */

__global__ __launch_bounds__(128) void flash_kernel(
    const float* __restrict__ q, const float* __restrict__ k,
    const float* __restrict__ v, float* __restrict__ out)
{
    extern __shared__ char smem_raw[];
    float4* Qs = (float4*)smem_raw;                       // [64][17]
    float4* Ks = (float4*)(smem_raw + 17408);             // [64][17]
    float4* Vs = (float4*)(smem_raw + 34816);             // [64][17]
    float*  Ps = (float*) (smem_raw + 52224);             // [64][65]

    const int tid = threadIdx.x;
    const int tx  = tid & 7;
    const int ty  = tid >> 3;
    const int r0  = blockIdx.x * 64;
    const int h   = blockIdx.y;
    const int b   = blockIdx.z;

    const float* qg = q + (long)(b * SQn + r0) * Dn + h * HDn;
    const float* kg = k + (long)(b * SKn) * Dn + h * HDn;
    const float* vg = v + (long)(b * SKn) * Dn + h * HDn;

#pragma unroll
    for (int i = 0; i < 8; i++) {
        const int idx = tid + i * 128;
        const int rr = idx >> 4, cc = idx & 15;
        float4 t = ((const float4*)(qg + (long)rr * Dn))[cc];
        t.x *= 0.125f; t.y *= 0.125f; t.z *= 0.125f; t.w *= 0.125f;
        Qs[rr * 17 + cc] = t;
    }

    u64 o2[4][4];
#pragma unroll
    for (int i = 0; i < 4; i++)
#pragma unroll
        for (int jp = 0; jp < 4; jp++) o2[i][jp] = 0ull;
    float m[4] = {-3.0e38f, -3.0e38f, -3.0e38f, -3.0e38f};
    float l[4] = {0.f, 0.f, 0.f, 0.f};

    for (int t0 = 0; t0 < SKn; t0 += 64) {
        __syncthreads();
#pragma unroll
        for (int i = 0; i < 8; i++) {
            const int idx = tid + i * 128;
            const int rr = idx >> 4, cc = idx & 15;
            Ks[rr * 17 + cc] = ((const float4*)(kg + (long)(t0 + rr) * Dn))[cc];
            Vs[rr * 17 + cc] = ((const float4*)(vg + (long)(t0 + rr) * Dn))[cc];
        }
        __syncthreads();

        u64 sc2[4][8];
#pragma unroll
        for (int i = 0; i < 4; i++)
#pragma unroll
            for (int j = 0; j < 8; j++) sc2[i][j] = 0ull;

#pragma unroll
        for (int d4 = 0; d4 < 16; d4++) {
            const ulonglong2 a0 = *(const ulonglong2*)&Qs[(4 * ty + 0) * 17 + d4];
            const ulonglong2 a1 = *(const ulonglong2*)&Qs[(4 * ty + 1) * 17 + d4];
            const ulonglong2 a2 = *(const ulonglong2*)&Qs[(4 * ty + 2) * 17 + d4];
            const ulonglong2 a3 = *(const ulonglong2*)&Qs[(4 * ty + 3) * 17 + d4];
#pragma unroll
            for (int j = 0; j < 8; j++) {
                const ulonglong2 kb = *(const ulonglong2*)&Ks[(tx + 8 * j) * 17 + d4];
                sc2[0][j] = fma2(a0.x, kb.x, sc2[0][j]);
                sc2[0][j] = fma2(a0.y, kb.y, sc2[0][j]);
                sc2[1][j] = fma2(a1.x, kb.x, sc2[1][j]);
                sc2[1][j] = fma2(a1.y, kb.y, sc2[1][j]);
                sc2[2][j] = fma2(a2.x, kb.x, sc2[2][j]);
                sc2[2][j] = fma2(a2.y, kb.y, sc2[2][j]);
                sc2[3][j] = fma2(a3.x, kb.x, sc2[3][j]);
                sc2[3][j] = fma2(a3.y, kb.y, sc2[3][j]);
            }
        }

        float sc[4][8];
#pragma unroll
        for (int i = 0; i < 4; i++)
#pragma unroll
            for (int j = 0; j < 8; j++) {
                const float2 t = unpack2(sc2[i][j]);
                sc[i][j] = t.x + t.y;
            }

        float fresc[4];
#pragma unroll
        for (int i = 0; i < 4; i++) {
            float pm = sc[i][0];
#pragma unroll
            for (int j = 1; j < 8; j++) pm = fmaxf(pm, sc[i][j]);
            pm = fmaxf(pm, __shfl_xor_sync(0xFFFFFFFFu, pm, 1));
            pm = fmaxf(pm, __shfl_xor_sync(0xFFFFFFFFu, pm, 2));
            pm = fmaxf(pm, __shfl_xor_sync(0xFFFFFFFFu, pm, 4));
            const float mnew = fmaxf(m[i], pm);
            const float f = __expf(m[i] - mnew);
            m[i] = mnew;
            float psum = 0.f;
#pragma unroll
            for (int j = 0; j < 8; j++) {
                const float p = __expf(sc[i][j] - mnew);
                psum += p;
                Ps[(4 * ty + i) * 65 + (tx + 8 * j)] = p;
            }
            psum += __shfl_xor_sync(0xFFFFFFFFu, psum, 1);
            psum += __shfl_xor_sync(0xFFFFFFFFu, psum, 2);
            psum += __shfl_xor_sync(0xFFFFFFFFu, psum, 4);
            l[i] = l[i] * f + psum;
            fresc[i] = f;
        }
#pragma unroll
        for (int i = 0; i < 4; i++) {
            const u64 f2 = pack_dup(fresc[i]);
#pragma unroll
            for (int jp = 0; jp < 4; jp++) o2[i][jp] = mul2(o2[i][jp], f2);
        }

        __syncthreads();

#pragma unroll
        for (int kk = 0; kk < 64; kk++) {
            const u64 p0 = pack_dup(Ps[(4 * ty + 0) * 65 + kk]);
            const u64 p1 = pack_dup(Ps[(4 * ty + 1) * 65 + kk]);
            const u64 p2 = pack_dup(Ps[(4 * ty + 2) * 65 + kk]);
            const u64 p3 = pack_dup(Ps[(4 * ty + 3) * 65 + kk]);
            const ulonglong2 v0 = *(const ulonglong2*)&Vs[kk * 17 + tx];
            const ulonglong2 v1 = *(const ulonglong2*)&Vs[kk * 17 + tx + 8];
            o2[0][0] = fma2(p0, v0.x, o2[0][0]);
            o2[0][1] = fma2(p0, v0.y, o2[0][1]);
            o2[0][2] = fma2(p0, v1.x, o2[0][2]);
            o2[0][3] = fma2(p0, v1.y, o2[0][3]);
            o2[1][0] = fma2(p1, v0.x, o2[1][0]);
            o2[1][1] = fma2(p1, v0.y, o2[1][1]);
            o2[1][2] = fma2(p1, v1.x, o2[1][2]);
            o2[1][3] = fma2(p1, v1.y, o2[1][3]);
            o2[2][0] = fma2(p2, v0.x, o2[2][0]);
            o2[2][1] = fma2(p2, v0.y, o2[2][1]);
            o2[2][2] = fma2(p2, v1.x, o2[2][2]);
            o2[2][3] = fma2(p2, v1.y, o2[2][3]);
            o2[3][0] = fma2(p3, v0.x, o2[3][0]);
            o2[3][1] = fma2(p3, v0.y, o2[3][1]);
            o2[3][2] = fma2(p3, v1.x, o2[3][2]);
            o2[3][3] = fma2(p3, v1.y, o2[3][3]);
        }
    }

#pragma unroll
    for (int i = 0; i < 4; i++) {
        const float inv = 1.f / l[i];
        const int row = r0 + 4 * ty + i;
        float* op = out + ((long)(b * SQn + row)) * Dn + h * HDn;
        const float2 t0 = unpack2(o2[i][0]);
        const float2 t1 = unpack2(o2[i][1]);
        const float2 t2 = unpack2(o2[i][2]);
        const float2 t3 = unpack2(o2[i][3]);
        float4 w0, w1;
        w0.x = t0.x * inv; w0.y = t0.y * inv; w0.z = t1.x * inv; w0.w = t1.y * inv;
        w1.x = t2.x * inv; w1.y = t2.y * inv; w1.z = t3.x * inv; w1.w = t3.y * inv;
        *(float4*)(op + 4 * tx)      = w0;
        *(float4*)(op + 32 + 4 * tx) = w1;
    }
}

// ---------------------------------------------------------------------------
extern "C" void kernel_launch(void* const* d_in, const int* in_sizes, int n_in,
                              void* d_out, int out_size)
{
    const float* x   = (const float*)d_in[0];
    const float* enc = (const float*)d_in[1];
    const float* Wq  = (const float*)d_in[2];
    const float* bq  = (const float*)d_in[3];
    const float* Wk  = (const float*)d_in[4];
    const float* bk  = (const float*)d_in[5];
    const float* Wv  = (const float*)d_in[6];
    const float* bv  = (const float*)d_in[7];
    const float* Wo  = (const float*)d_in[8];
    const float* bo  = (const float*)d_in[9];
    float* out = (float*)d_out;

    float *qp, *kp, *vp, *aop;
    cudaGetSymbolAddress((void**)&qp,  g_q);
    cudaGetSymbolAddress((void**)&kp,  g_k);
    cudaGetSymbolAddress((void**)&vp,  g_v);
    cudaGetSymbolAddress((void**)&aop, g_ao);
    __nv_bfloat16 (*wh)[Nn * Kn];
    __nv_bfloat16 (*wl)[Nn * Kn];
    __nv_bfloat16 (*ah)[Mn * Dn];
    __nv_bfloat16 (*al)[Mn * Dn];
    cudaGetSymbolAddress((void**)&wh, g_wh);
    cudaGetSymbolAddress((void**)&wl, g_wl);
    cudaGetSymbolAddress((void**)&ah, g_ah);
    cudaGetSymbolAddress((void**)&al, g_al);

    cudaFuncSetAttribute(tc_gemm,
                         cudaFuncAttributeMaxDynamicSharedMemorySize, GM_SMEM);
    cudaFuncSetAttribute(flash_kernel,
                         cudaFuncAttributeMaxDynamicSharedMemorySize, FL_SMEM);

    dim3 tgrid(16, 16);
    wsplit_kernel<0><<<tgrid, 256>>>(Wq, wh[0], wl[0]);
    wsplit_kernel<0><<<tgrid, 256>>>(Wk, wh[1], wl[1]);
    wsplit_kernel<0><<<tgrid, 256>>>(Wv, wh[2], wl[2]);
    wsplit_kernel<1><<<tgrid, 256>>>(Wo, wh[3], wl[3]);
    asplit_kernel<<<4096, 256>>>(x,   ah[0], al[0]);
    asplit_kernel<<<4096, 256>>>(enc, ah[1], al[1]);

    dim3 ggrid(Nn / 128, Mn / 128);   // (8, 32)
    tc_gemm<<<ggrid, 256, GM_SMEM>>>(ah[0], al[0], wh[0], wl[0], bq, qp);
    tc_gemm<<<ggrid, 256, GM_SMEM>>>(ah[1], al[1], wh[1], wl[1], bk, kp);
    tc_gemm<<<ggrid, 256, GM_SMEM>>>(ah[1], al[1], wh[2], wl[2], bv, vp);

    flash_kernel<<<dim3(SQn / 64, Hn, Bb), 128, FL_SMEM>>>(qp, kp, vp, aop);

    asplit_kernel<<<4096, 256>>>(aop, ah[2], al[2]);
    tc_gemm<<<ggrid, 256, GM_SMEM>>>(ah[2], al[2], wh[3], wl[3], bo, out);
}

// round 12
// speedup vs baseline: 7.5986x; 1.6712x over previous
#include <cuda_runtime.h>
#include <cuda_bf16.h>

typedef unsigned long long u64;
typedef unsigned int u32;

// Problem dims (fixed by the reference)
constexpr int Bb  = 2;
constexpr int SQn = 2048;
constexpr int SKn = 2048;
constexpr int Dn  = 1024;
constexpr int Hn  = 16;
constexpr int HDn = 64;

constexpr int Mn = Bb * SQn;   // 4096
constexpr int Nn = 1024;
constexpr int Kn = 1024;

// Scratch (static device globals; no dynamic allocation allowed)
__device__ __nv_bfloat16 g_wh[4][Nn * Kn];    // transposed weights, hi
__device__ __nv_bfloat16 g_wl[4][Nn * Kn];    // transposed weights, lo
__device__ __nv_bfloat16 g_ah[2][Mn * Dn];    // activations hi: x, enc
__device__ __nv_bfloat16 g_al[2][Mn * Dn];    // activations lo
__device__ __nv_bfloat16 g_qh[Mn * Dn], g_ql[Mn * Dn];   // q hi/lo (pre-scaled)
__device__ __nv_bfloat16 g_kh[Mn * Dn], g_kl[Mn * Dn];
__device__ __nv_bfloat16 g_vh[Mn * Dn], g_vl[Mn * Dn];
__device__ __nv_bfloat16 g_aoh[Mn * Dn], g_aol[Mn * Dn]; // attention out hi/lo

// ============================ PTX helpers ===================================
__device__ __forceinline__ u32 smem_u32(const void* p) {
    u32 a;
    asm("{ .reg .u64 t; cvta.to.shared.u64 t, %1; cvt.u32.u64 %0, t; }"
        : "=r"(a) : "l"(p));
    return a;
}
__device__ __forceinline__ void ldsm4(u32* r, u32 addr) {
    asm volatile("ldmatrix.sync.aligned.m8n8.x4.shared.b16 {%0,%1,%2,%3}, [%4];"
                 : "=r"(r[0]), "=r"(r[1]), "=r"(r[2]), "=r"(r[3]) : "r"(addr));
}
__device__ __forceinline__ void ldsm4t(u32* r, u32 addr) {
    asm volatile("ldmatrix.sync.aligned.m8n8.x4.trans.shared.b16 {%0,%1,%2,%3}, [%4];"
                 : "=r"(r[0]), "=r"(r[1]), "=r"(r[2]), "=r"(r[3]) : "r"(addr));
}
__device__ __forceinline__ void mma_bf16(float* d, const u32* a, u32 b0, u32 b1) {
    asm volatile("mma.sync.aligned.m16n8k16.row.col.f32.bf16.bf16.f32 "
                 "{%0,%1,%2,%3}, {%4,%5,%6,%7}, {%8,%9}, {%0,%1,%2,%3};"
                 : "+f"(d[0]), "+f"(d[1]), "+f"(d[2]), "+f"(d[3])
                 : "r"(a[0]), "r"(a[1]), "r"(a[2]), "r"(a[3]), "r"(b0), "r"(b1));
}
__device__ __forceinline__ void cpa16(u32 saddr, const void* g) {
    asm volatile("cp.async.cg.shared.global [%0], [%1], 16;"
                 :: "r"(saddr), "l"(g) : "memory");
}
// pack two fp32 -> bf16x2 (hi goes to upper 16 bits)
__device__ __forceinline__ u32 cvt2(float hi, float lo) {
    u32 d;
    asm("cvt.rn.bf16x2.f32 %0, %1, %2;" : "=r"(d) : "f"(hi), "f"(lo));
    return d;
}
__device__ __forceinline__ float blo(u32 r) { return __uint_as_float(r << 16); }
__device__ __forceinline__ float bhi(u32 r) { return __uint_as_float(r & 0xFFFF0000u); }

// ---------------------------------------------------------------------------
// Weight pre-pass: transpose to Wt[n][k] and split fp32 -> bf16 hi + lo.
// ---------------------------------------------------------------------------
template <int MODE>
__global__ __launch_bounds__(256) void wsplit_kernel(
    const float* __restrict__ W, __nv_bfloat16* __restrict__ Th,
    __nv_bfloat16* __restrict__ Tl)
{
    __shared__ float tile[64][65];
    const int k0 = blockIdx.x * 64;
    const int by = blockIdx.y;
    const int tid = threadIdx.x;
#pragma unroll
    for (int i = 0; i < 16; i++) {
        const int idx = tid + i * 256;
        const int kk = idx >> 6, e = idx & 63;
        long off;
        if (MODE == 0) off = (long)by * 65536 + (long)(k0 + kk) * 64 + e;
        else           off = (long)(k0 + kk) * Nn + by * 64 + e;
        tile[kk][e] = W[off];
    }
    __syncthreads();
#pragma unroll
    for (int i = 0; i < 16; i++) {
        const int idx = tid + i * 256;
        const int e = idx >> 6, kk = idx & 63;
        const float v = tile[kk][e];
        const __nv_bfloat16 h = __float2bfloat16(v);
        const __nv_bfloat16 l = __float2bfloat16(v - __bfloat162float(h));
        const long o = (long)(by * 64 + e) * Kn + k0 + kk;
        Th[o] = h;
        Tl[o] = l;
    }
}

// ---------------------------------------------------------------------------
// Activation split: fp32 -> bf16 hi + lo (elementwise, float4-wide).
// ---------------------------------------------------------------------------
__global__ __launch_bounds__(256) void asplit_kernel(
    const float* __restrict__ in, __nv_bfloat16* __restrict__ h,
    __nv_bfloat16* __restrict__ l)
{
    const long i = ((long)blockIdx.x * 256 + threadIdx.x) * 4;
    const float4 t = *(const float4*)(in + i);
    const u32 h0 = cvt2(t.y, t.x);
    const u32 h1 = cvt2(t.w, t.z);
    const u32 l0 = cvt2(t.y - bhi(h0), t.x - blo(h0));
    const u32 l1 = cvt2(t.w - bhi(h1), t.z - blo(h1));
    *(uint2*)(h + i) = make_uint2(h0, h1);
    *(uint2*)(l + i) = make_uint2(l0, l1);
}

// ---------------------------------------------------------------------------
// Tensor-core split-bf16 GEMM (HMMA): C = A * Wt^T + bias
// OSPLIT=0: C fp32 row-major.  OSPLIT=1: C written as bf16 hi/lo pair arrays,
// scaled by `scale` after bias (used to fold 0.125*log2e into Q).
// ---------------------------------------------------------------------------
constexpr int GM_SMEM = 132096;

template <int OSPLIT>
__global__ __launch_bounds__(256) void tc_gemm(
    const __nv_bfloat16* __restrict__ Ah, const __nv_bfloat16* __restrict__ Al,
    const __nv_bfloat16* __restrict__ Bh, const __nv_bfloat16* __restrict__ Bl,
    const float* __restrict__ bias, float* __restrict__ Cf,
    __nv_bfloat16* __restrict__ Ch, __nv_bfloat16* __restrict__ Cl,
    float scale)
{
    extern __shared__ char sm[];
    const u32 sbase = smem_u32(sm);
    const u32 abase = (sbase + 1023) & ~1023u;
    const int tid = threadIdx.x;
    const int m0 = blockIdx.y * 128, n0 = blockIdx.x * 128;

    const __nv_bfloat16* srcs[4] = {
        Ah + (long)m0 * Kn, Al + (long)m0 * Kn,
        Bh + (long)n0 * Kn, Bl + (long)n0 * Kn };

    auto stage = [&](int c, int b) {
        const u32 dst = abase + b * 65536;
#pragma unroll
        for (int tile = 0; tile < 4; tile++) {
            const __nv_bfloat16* src = srcs[tile] + c * 64;
#pragma unroll
            for (int i = 0; i < 4; i++) {
                const int q = tid + i * 256;
                const int row = q >> 3, qd = q & 7;
                cpa16(dst + tile * 16384 + row * 128 + ((qd * 16) ^ ((row & 7) << 4)),
                      src + (long)row * Kn + qd * 8);
            }
        }
    };

    const int lane = tid & 31, wid = tid >> 5;
    const int wm = wid >> 1, wn = wid & 1;
    const int Rr = wm * 32, Ncol = wn * 64;
    const int lrow = (lane & 7) + ((lane >> 3) & 1) * 8;
    const int lkb  = (lane >> 4) * 16;
    const int xorm = (lrow & 7) << 4;

    float acc[2][8][4];
#pragma unroll
    for (int mb = 0; mb < 2; mb++)
#pragma unroll
        for (int nb = 0; nb < 8; nb++)
#pragma unroll
            for (int r = 0; r < 4; r++) acc[mb][nb][r] = 0.f;

    stage(0, 0);
    asm volatile("cp.async.commit_group;" ::: "memory");

    for (int c = 0; c < 16; c++) {
        if (c < 15) {
            stage(c + 1, (c + 1) & 1);
            asm volatile("cp.async.commit_group;" ::: "memory");
            asm volatile("cp.async.wait_group 1;" ::: "memory");
        } else {
            asm volatile("cp.async.wait_group 0;" ::: "memory");
        }
        __syncthreads();

        const u32 sb = abase + (c & 1) * 65536;
        const u32 arow0 = sb + (Rr + lrow) * 128;
        const u32 brow0 = sb + 32768 + (Ncol + lrow) * 128;
#pragma unroll
        for (int t = 0; t < 4; t++) {
            const u32 cb = (u32)((32 * t + lkb) ^ xorm);
            u32 ah[2][4], al[2][4];
#pragma unroll
            for (int mb = 0; mb < 2; mb++) {
                ldsm4(ah[mb], arow0 + mb * 2048 + cb);
                ldsm4(al[mb], arow0 + 16384 + mb * 2048 + cb);
            }
#pragma unroll
            for (int g = 0; g < 4; g++) {
                u32 bh[4], bl[4];
                ldsm4(bh, brow0 + g * 2048 + cb);
                ldsm4(bl, brow0 + 16384 + g * 2048 + cb);
#pragma unroll
                for (int mb = 0; mb < 2; mb++) {
                    mma_bf16(acc[mb][2 * g],     ah[mb], bh[0], bh[2]);
                    mma_bf16(acc[mb][2 * g],     ah[mb], bl[0], bl[2]);
                    mma_bf16(acc[mb][2 * g],     al[mb], bh[0], bh[2]);
                    mma_bf16(acc[mb][2 * g + 1], ah[mb], bh[1], bh[3]);
                    mma_bf16(acc[mb][2 * g + 1], ah[mb], bl[1], bl[3]);
                    mma_bf16(acc[mb][2 * g + 1], al[mb], bh[1], bh[3]);
                }
            }
        }
        __syncthreads();
    }

#pragma unroll
    for (int mb = 0; mb < 2; mb++) {
        const int row = m0 + Rr + 16 * mb + (lane >> 2);
#pragma unroll
        for (int nb = 0; nb < 8; nb++) {
            const int col = n0 + Ncol + nb * 8 + (lane & 3) * 2;
            const float2 bb = *(const float2*)(bias + col);
            float v0 = acc[mb][nb][0] + bb.x, v1 = acc[mb][nb][1] + bb.y;
            float v2 = acc[mb][nb][2] + bb.x, v3 = acc[mb][nb][3] + bb.y;
            if (OSPLIT) {
                v0 *= scale; v1 *= scale; v2 *= scale; v3 *= scale;
                const u32 hi0 = cvt2(v1, v0);
                const u32 lo0 = cvt2(v1 - bhi(hi0), v0 - blo(hi0));
                const u32 hi1 = cvt2(v3, v2);
                const u32 lo1 = cvt2(v3 - bhi(hi1), v2 - blo(hi1));
                *(u32*)(Ch + (long)row * Nn + col)       = hi0;
                *(u32*)(Cl + (long)row * Nn + col)       = lo0;
                *(u32*)(Ch + (long)(row + 8) * Nn + col) = hi1;
                *(u32*)(Cl + (long)(row + 8) * Nn + col) = lo1;
            } else {
                *(float2*)(Cf + (long)row * Nn + col)       = make_float2(v0, v1);
                *(float2*)(Cf + (long)(row + 8) * Nn + col) = make_float2(v2, v3);
            }
        }
    }
}

// ---------------------------------------------------------------------------
// Tensor-core flash attention (HMMA, split-bf16, base-2 softmax).
// CTA = 128 q-rows x one (b,h); 8 warps x 16 rows. Key tiles of 64,
// K/V double-buffered via cp.async. Q fragments live in registers.
// P fragments come straight from the S accumulators (no smem round trip).
// Writes attention-out as bf16 hi/lo for the final GEMM.
// ---------------------------------------------------------------------------
constexpr int FL_SMEM = 99328;   // 1KB align + Qh/Ql 32KB + 2 x 32KB K/V bufs

__global__ __launch_bounds__(256) void flash_tc(
    const __nv_bfloat16* __restrict__ qh_g, const __nv_bfloat16* __restrict__ ql_g,
    const __nv_bfloat16* __restrict__ kh_g, const __nv_bfloat16* __restrict__ kl_g,
    const __nv_bfloat16* __restrict__ vh_g, const __nv_bfloat16* __restrict__ vl_g,
    __nv_bfloat16* __restrict__ aoh, __nv_bfloat16* __restrict__ aol)
{
    extern __shared__ char sm[];
    const u32 sbase = smem_u32(sm);
    const u32 abase = (sbase + 1023) & ~1023u;
    const int tid = threadIdx.x, lane = tid & 31, wid = tid >> 5;
    const int r0 = blockIdx.x * 128;
    const int h  = blockIdx.y;
    const int b  = blockIdx.z;
    const int Rr = wid * 16;

    const long qoff = ((long)(b * SQn + r0)) * Dn + h * HDn;
    const long koff0 = ((long)(b * SKn)) * Dn + h * HDn;

    // Stage Q hi/lo (one time): 128 rows x 64 bf16, swizzled
#pragma unroll
    for (int i = 0; i < 4; i++) {
        const int q = tid + i * 256;
        const int row = q >> 3, qd = q & 7;
        const u32 dst = abase + row * 128 + ((qd * 16) ^ ((row & 7) << 4));
        const long g = qoff + (long)row * Dn + qd * 8;
        cpa16(dst, qh_g + g);
        cpa16(dst + 16384, ql_g + g);
    }
    asm volatile("cp.async.commit_group;" ::: "memory");

    // Stage K/V tile 0
    auto stageKV = [&](int c, int buf) {
        const u32 dst0 = abase + 32768 + buf * 32768;
        const long koff = koff0 + (long)(c * 64) * Dn;
#pragma unroll
        for (int i = 0; i < 2; i++) {
            const int q = tid + i * 256;
            const int row = q >> 3, qd = q & 7;
            const u32 so = row * 128 + ((qd * 16) ^ ((row & 7) << 4));
            const long g = koff + (long)row * Dn + qd * 8;
            cpa16(dst0 + so,         kh_g + g);
            cpa16(dst0 + 8192 + so,  kl_g + g);
            cpa16(dst0 + 16384 + so, vh_g + g);
            cpa16(dst0 + 24576 + so, vl_g + g);
        }
    };
    stageKV(0, 0);
    asm volatile("cp.async.commit_group;" ::: "memory");
    asm volatile("cp.async.wait_group 1;" ::: "memory");   // Q ready
    __syncthreads();

    // Q fragments -> registers (kept for whole kernel)
    const int lrow = (lane & 7) + ((lane >> 3) & 1) * 8;
    const int lkb  = (lane >> 4) * 16;
    u32 qh[4][4], ql[4][4];
#pragma unroll
    for (int t = 0; t < 4; t++) {
        const u32 ad = abase + (Rr + lrow) * 128 +
                       (((u32)(t * 32 + lkb)) ^ ((lrow & 7) << 4));
        ldsm4(qh[t], ad);
        ldsm4(ql[t], ad + 16384);
    }

    float O[8][4];
#pragma unroll
    for (int nb = 0; nb < 8; nb++)
#pragma unroll
        for (int r = 0; r < 4; r++) O[nb][r] = 0.f;
    float m0 = -3.0e38f, m1 = -3.0e38f, l0 = 0.f, l1 = 0.f;

    for (int c = 0; c < 32; c++) {
        if (c < 31) {
            stageKV(c + 1, (c + 1) & 1);
            asm volatile("cp.async.commit_group;" ::: "memory");
            asm volatile("cp.async.wait_group 1;" ::: "memory");
        } else {
            asm volatile("cp.async.wait_group 0;" ::: "memory");
        }
        __syncthreads();

        const u32 kb = abase + 32768 + (c & 1) * 32768;

        // ---- S = Q . K^T (3 products, fp32 accum) ----
        float S[8][4];
#pragma unroll
        for (int nb = 0; nb < 8; nb++)
#pragma unroll
            for (int r = 0; r < 4; r++) S[nb][r] = 0.f;

#pragma unroll
        for (int t = 0; t < 4; t++) {
            const u32 cb = (((u32)(t * 32 + lkb)) ^ ((lrow & 7) << 4));
#pragma unroll
            for (int g = 0; g < 4; g++) {
                u32 kh_[4], kl_[4];
                const u32 ad = kb + (g * 16 + lrow) * 128 + cb;
                ldsm4(kh_, ad);
                ldsm4(kl_, ad + 8192);
                mma_bf16(S[2 * g],     qh[t], kh_[0], kh_[2]);
                mma_bf16(S[2 * g],     qh[t], kl_[0], kl_[2]);
                mma_bf16(S[2 * g],     ql[t], kh_[0], kh_[2]);
                mma_bf16(S[2 * g + 1], qh[t], kh_[1], kh_[3]);
                mma_bf16(S[2 * g + 1], qh[t], kl_[1], kl_[3]);
                mma_bf16(S[2 * g + 1], ql[t], kh_[1], kh_[3]);
            }
        }

        // ---- online softmax (base 2; scale folded into Q) ----
        float mx0 = -3.0e38f, mx1 = -3.0e38f;
#pragma unroll
        for (int nb = 0; nb < 8; nb++) {
            mx0 = fmaxf(mx0, fmaxf(S[nb][0], S[nb][1]));
            mx1 = fmaxf(mx1, fmaxf(S[nb][2], S[nb][3]));
        }
        mx0 = fmaxf(mx0, __shfl_xor_sync(0xFFFFFFFFu, mx0, 1));
        mx0 = fmaxf(mx0, __shfl_xor_sync(0xFFFFFFFFu, mx0, 2));
        mx1 = fmaxf(mx1, __shfl_xor_sync(0xFFFFFFFFu, mx1, 1));
        mx1 = fmaxf(mx1, __shfl_xor_sync(0xFFFFFFFFu, mx1, 2));
        const float mn0 = fmaxf(m0, mx0), mn1 = fmaxf(m1, mx1);
        const float f0 = exp2f(m0 - mn0), f1 = exp2f(m1 - mn1);
        m0 = mn0; m1 = mn1;
        float s0 = 0.f, s1 = 0.f;
#pragma unroll
        for (int nb = 0; nb < 8; nb++) {
            S[nb][0] = exp2f(S[nb][0] - m0); s0 += S[nb][0];
            S[nb][1] = exp2f(S[nb][1] - m0); s0 += S[nb][1];
            S[nb][2] = exp2f(S[nb][2] - m1); s1 += S[nb][2];
            S[nb][3] = exp2f(S[nb][3] - m1); s1 += S[nb][3];
        }
        s0 += __shfl_xor_sync(0xFFFFFFFFu, s0, 1);
        s0 += __shfl_xor_sync(0xFFFFFFFFu, s0, 2);
        s1 += __shfl_xor_sync(0xFFFFFFFFu, s1, 1);
        s1 += __shfl_xor_sync(0xFFFFFFFFu, s1, 2);
        l0 = l0 * f0 + s0;
        l1 = l1 * f1 + s1;
#pragma unroll
        for (int nb = 0; nb < 8; nb++) {
            O[nb][0] *= f0; O[nb][1] *= f0;
            O[nb][2] *= f1; O[nb][3] *= f1;
        }

        // ---- O += P . V (P from S regs; V via ldmatrix.trans) ----
        const u32 vb = kb + 16384;
        const int vkey0 = ((lane >> 3) & 1) * 8 + (lane & 7);
        const int vcolb = (lane >> 4) * 16;
#pragma unroll
        for (int t = 0; t < 4; t++) {
            u32 ph[4], pl[4];
            ph[0] = cvt2(S[2 * t][1],     S[2 * t][0]);
            ph[1] = cvt2(S[2 * t][3],     S[2 * t][2]);
            ph[2] = cvt2(S[2 * t + 1][1], S[2 * t + 1][0]);
            ph[3] = cvt2(S[2 * t + 1][3], S[2 * t + 1][2]);
            pl[0] = cvt2(S[2 * t][1] - bhi(ph[0]),     S[2 * t][0] - blo(ph[0]));
            pl[1] = cvt2(S[2 * t][3] - bhi(ph[1]),     S[2 * t][2] - blo(ph[1]));
            pl[2] = cvt2(S[2 * t + 1][1] - bhi(ph[2]), S[2 * t + 1][0] - blo(ph[2]));
            pl[3] = cvt2(S[2 * t + 1][3] - bhi(ph[3]), S[2 * t + 1][2] - blo(ph[3]));

            const int vkey = t * 16 + vkey0;
            const u32 vrow = vb + vkey * 128;
            const u32 vxor = (vkey & 7) << 4;
#pragma unroll
            for (int np = 0; np < 4; np++) {
                u32 vh_[4], vl_[4];
                const u32 ad = vrow + (((u32)(np * 32 + vcolb)) ^ vxor);
                ldsm4t(vh_, ad);
                ldsm4t(vl_, ad + 8192);
                mma_bf16(O[2 * np],     ph, vh_[0], vh_[1]);
                mma_bf16(O[2 * np],     ph, vl_[0], vl_[1]);
                mma_bf16(O[2 * np],     pl, vh_[0], vh_[1]);
                mma_bf16(O[2 * np + 1], ph, vh_[2], vh_[3]);
                mma_bf16(O[2 * np + 1], ph, vl_[2], vl_[3]);
                mma_bf16(O[2 * np + 1], pl, vh_[2], vh_[3]);
            }
        }
        __syncthreads();
    }

    // ---- epilogue: normalize, split to bf16 hi/lo, store ----
    const float inv0 = 1.f / l0, inv1 = 1.f / l1;
    const int row = r0 + Rr + (lane >> 2);
    const long ob0 = ((long)(b * SQn + row)) * Dn + h * HDn + 2 * (lane & 3);
    const long ob1 = ob0 + 8 * Dn;
#pragma unroll
    for (int nb = 0; nb < 8; nb++) {
        const float o0 = O[nb][0] * inv0, o1 = O[nb][1] * inv0;
        const float o2 = O[nb][2] * inv1, o3 = O[nb][3] * inv1;
        const u32 hi0 = cvt2(o1, o0);
        const u32 lo0 = cvt2(o1 - bhi(hi0), o0 - blo(hi0));
        const u32 hi1 = cvt2(o3, o2);
        const u32 lo1 = cvt2(o3 - bhi(hi1), o2 - blo(hi1));
        *(u32*)(aoh + ob0 + nb * 8) = hi0;
        *(u32*)(aol + ob0 + nb * 8) = lo0;
        *(u32*)(aoh + ob1 + nb * 8) = hi1;
        *(u32*)(aol + ob1 + nb * 8) = lo1;
    }
}

// ---------------------------------------------------------------------------
extern "C" void kernel_launch(void* const* d_in, const int* in_sizes, int n_in,
                              void* d_out, int out_size)
{
    const float* x   = (const float*)d_in[0];
    const float* enc = (const float*)d_in[1];
    const float* Wq  = (const float*)d_in[2];
    const float* bq  = (const float*)d_in[3];
    const float* Wk  = (const float*)d_in[4];
    const float* bk  = (const float*)d_in[5];
    const float* Wv  = (const float*)d_in[6];
    const float* bv  = (const float*)d_in[7];
    const float* Wo  = (const float*)d_in[8];
    const float* bo  = (const float*)d_in[9];
    float* out = (float*)d_out;

    __nv_bfloat16 (*wh)[Nn * Kn]; __nv_bfloat16 (*wl)[Nn * Kn];
    __nv_bfloat16 (*ah)[Mn * Dn]; __nv_bfloat16 (*al)[Mn * Dn];
    __nv_bfloat16 *qh, *ql, *kh, *kl, *vh, *vl, *aoh, *aol;
    cudaGetSymbolAddress((void**)&wh, g_wh);
    cudaGetSymbolAddress((void**)&wl, g_wl);
    cudaGetSymbolAddress((void**)&ah, g_ah);
    cudaGetSymbolAddress((void**)&al, g_al);
    cudaGetSymbolAddress((void**)&qh, g_qh);
    cudaGetSymbolAddress((void**)&ql, g_ql);
    cudaGetSymbolAddress((void**)&kh, g_kh);
    cudaGetSymbolAddress((void**)&kl, g_kl);
    cudaGetSymbolAddress((void**)&vh, g_vh);
    cudaGetSymbolAddress((void**)&vl, g_vl);
    cudaGetSymbolAddress((void**)&aoh, g_aoh);
    cudaGetSymbolAddress((void**)&aol, g_aol);

    cudaFuncSetAttribute(tc_gemm<0>,
                         cudaFuncAttributeMaxDynamicSharedMemorySize, GM_SMEM);
    cudaFuncSetAttribute(tc_gemm<1>,
                         cudaFuncAttributeMaxDynamicSharedMemorySize, GM_SMEM);
    cudaFuncSetAttribute(flash_tc,
                         cudaFuncAttributeMaxDynamicSharedMemorySize, FL_SMEM);

    dim3 tgrid(16, 16);
    wsplit_kernel<0><<<tgrid, 256>>>(Wq, wh[0], wl[0]);
    wsplit_kernel<0><<<tgrid, 256>>>(Wk, wh[1], wl[1]);
    wsplit_kernel<0><<<tgrid, 256>>>(Wv, wh[2], wl[2]);
    wsplit_kernel<1><<<tgrid, 256>>>(Wo, wh[3], wl[3]);
    asplit_kernel<<<4096, 256>>>(x,   ah[0], al[0]);
    asplit_kernel<<<4096, 256>>>(enc, ah[1], al[1]);

    const float qscale = 0.125f * 1.44269504088896f;   // 1/sqrt(HD) * log2(e)
    dim3 ggrid(Nn / 128, Mn / 128);   // (8, 32)
    tc_gemm<1><<<ggrid, 256, GM_SMEM>>>(ah[0], al[0], wh[0], wl[0], bq,
                                        nullptr, qh, ql, qscale);
    tc_gemm<1><<<ggrid, 256, GM_SMEM>>>(ah[1], al[1], wh[1], wl[1], bk,
                                        nullptr, kh, kl, 1.0f);
    tc_gemm<1><<<ggrid, 256, GM_SMEM>>>(ah[1], al[1], wh[2], wl[2], bv,
                                        nullptr, vh, vl, 1.0f);

    flash_tc<<<dim3(SQn / 128, Hn, Bb), 256, FL_SMEM>>>(qh, ql, kh, kl, vh, vl,
                                                        aoh, aol);

    tc_gemm<0><<<ggrid, 256, GM_SMEM>>>(aoh, aol, wh[3], wl[3], bo,
                                        out, nullptr, nullptr, 1.0f);
}

// round 14
// speedup vs baseline: 7.9540x; 1.0468x over previous
#include <cuda_runtime.h>
#include <cuda_bf16.h>

typedef unsigned long long u64;
typedef unsigned int u32;

// Problem dims (fixed by the reference)
constexpr int Bb  = 2;
constexpr int SQn = 2048;
constexpr int SKn = 2048;
constexpr int Dn  = 1024;
constexpr int Hn  = 16;
constexpr int HDn = 64;

constexpr int Mn = Bb * SQn;   // 4096
constexpr int Nn = 1024;
constexpr int Kn = 1024;

// Scratch (static device globals; no dynamic allocation allowed)
__device__ __nv_bfloat16 g_wh[4][Nn * Kn];    // transposed weights, hi
__device__ __nv_bfloat16 g_wl[4][Nn * Kn];    // transposed weights, lo
__device__ __nv_bfloat16 g_ah[2][Mn * Dn];    // activations hi: x, enc
__device__ __nv_bfloat16 g_al[2][Mn * Dn];    // activations lo
__device__ __nv_bfloat16 g_qh[Mn * Dn], g_ql[Mn * Dn];   // q hi/lo (pre-scaled)
__device__ __nv_bfloat16 g_kh[Mn * Dn], g_kl[Mn * Dn];
__device__ __nv_bfloat16 g_vh[Mn * Dn], g_vl[Mn * Dn];
__device__ __nv_bfloat16 g_aoh[Mn * Dn], g_aol[Mn * Dn]; // attention out hi/lo

// ============================ PTX helpers ===================================
__device__ __forceinline__ u32 smem_u32(const void* p) {
    u32 a;
    asm("{ .reg .u64 t; cvta.to.shared.u64 t, %1; cvt.u32.u64 %0, t; }"
        : "=r"(a) : "l"(p));
    return a;
}
__device__ __forceinline__ void ldsm4(u32* r, u32 addr) {
    asm volatile("ldmatrix.sync.aligned.m8n8.x4.shared.b16 {%0,%1,%2,%3}, [%4];"
                 : "=r"(r[0]), "=r"(r[1]), "=r"(r[2]), "=r"(r[3]) : "r"(addr));
}
__device__ __forceinline__ void ldsm4t(u32* r, u32 addr) {
    asm volatile("ldmatrix.sync.aligned.m8n8.x4.trans.shared.b16 {%0,%1,%2,%3}, [%4];"
                 : "=r"(r[0]), "=r"(r[1]), "=r"(r[2]), "=r"(r[3]) : "r"(addr));
}
__device__ __forceinline__ void mma_bf16(float* d, const u32* a, u32 b0, u32 b1) {
    asm volatile("mma.sync.aligned.m16n8k16.row.col.f32.bf16.bf16.f32 "
                 "{%0,%1,%2,%3}, {%4,%5,%6,%7}, {%8,%9}, {%0,%1,%2,%3};"
                 : "+f"(d[0]), "+f"(d[1]), "+f"(d[2]), "+f"(d[3])
                 : "r"(a[0]), "r"(a[1]), "r"(a[2]), "r"(a[3]), "r"(b0), "r"(b1));
}
__device__ __forceinline__ void cpa16(u32 saddr, const void* g) {
    asm volatile("cp.async.cg.shared.global [%0], [%1], 16;"
                 :: "r"(saddr), "l"(g) : "memory");
}
// pack two fp32 -> bf16x2 (hi goes to upper 16 bits)
__device__ __forceinline__ u32 cvt2(float hi, float lo) {
    u32 d;
    asm("cvt.rn.bf16x2.f32 %0, %1, %2;" : "=r"(d) : "f"(hi), "f"(lo));
    return d;
}
__device__ __forceinline__ float blo(u32 r) { return __uint_as_float(r << 16); }
__device__ __forceinline__ float bhi(u32 r) { return __uint_as_float(r & 0xFFFF0000u); }

// ---------------------------------------------------------------------------
// Weight pre-pass (merged): z = 0..2 -> Wq/Wk/Wv ([H,D,HD]); z = 3 -> Wo ([K,N]).
// Transpose to Wt[n][k] and split fp32 -> bf16 hi + lo.
// ---------------------------------------------------------------------------
__global__ __launch_bounds__(256) void wsplit_all(
    const float* __restrict__ W0, const float* __restrict__ W1,
    const float* __restrict__ W2, const float* __restrict__ W3,
    __nv_bfloat16* __restrict__ Th0, __nv_bfloat16* __restrict__ Tl0)
{
    __shared__ float tile[64][65];
    const int z  = blockIdx.z;
    const float* W = (z == 0) ? W0 : (z == 1) ? W1 : (z == 2) ? W2 : W3;
    __nv_bfloat16* Th = Th0 + (long)z * Nn * Kn;
    __nv_bfloat16* Tl = Tl0 + (long)z * Nn * Kn;
    const int k0 = blockIdx.x * 64;
    const int by = blockIdx.y;
    const int tid = threadIdx.x;
#pragma unroll
    for (int i = 0; i < 16; i++) {
        const int idx = tid + i * 256;
        const int kk = idx >> 6, e = idx & 63;
        long off;
        if (z < 3) off = (long)by * 65536 + (long)(k0 + kk) * 64 + e;
        else       off = (long)(k0 + kk) * Nn + by * 64 + e;
        tile[kk][e] = W[off];
    }
    __syncthreads();
#pragma unroll
    for (int i = 0; i < 16; i++) {
        const int idx = tid + i * 256;
        const int e = idx >> 6, kk = idx & 63;
        const float v = tile[kk][e];
        const __nv_bfloat16 h = __float2bfloat16(v);
        const __nv_bfloat16 l = __float2bfloat16(v - __bfloat162float(h));
        const long o = (long)(by * 64 + e) * Kn + k0 + kk;
        Th[o] = h;
        Tl[o] = l;
    }
}

// ---------------------------------------------------------------------------
// Activation split (merged x + enc): 8192 blocks; first 4096 -> x, rest -> enc.
// ---------------------------------------------------------------------------
__global__ __launch_bounds__(256) void asplit_all(
    const float* __restrict__ x, const float* __restrict__ enc,
    __nv_bfloat16* __restrict__ h0, __nv_bfloat16* __restrict__ l0)
{
    const int z = (blockIdx.x >= 4096) ? 1 : 0;
    const float* in = z ? enc : x;
    __nv_bfloat16* h = h0 + (long)z * Mn * Dn;
    __nv_bfloat16* l = l0 + (long)z * Mn * Dn;
    const long i = ((long)(blockIdx.x - z * 4096) * 256 + threadIdx.x) * 4;
    const float4 t = *(const float4*)(in + i);
    const u32 p0 = cvt2(t.y, t.x);
    const u32 p1 = cvt2(t.w, t.z);
    const u32 q0 = cvt2(t.y - bhi(p0), t.x - blo(p0));
    const u32 q1 = cvt2(t.w - bhi(p1), t.z - blo(p1));
    *(uint2*)(h + i) = make_uint2(p0, p1);
    *(uint2*)(l + i) = make_uint2(q0, q1);
}

// ---------------------------------------------------------------------------
// Tensor-core split-bf16 GEMM (HMMA): C = A * Wt^T + bias
// CTA tile 128x256, BK=64, 8 warps as 2m x 4n, warp tile 64x64.
// gridDim.z selects a GemmJob (QKV fused in one launch).
// OSPLIT=0: C fp32 row-major.  OSPLIT=1: C as bf16 hi/lo pair arrays * scale.
// ---------------------------------------------------------------------------
struct GemmJob {
    const __nv_bfloat16 *Ah, *Al, *Bh, *Bl;
    const float* bias;
    float* Cf;
    __nv_bfloat16 *Ch, *Cl;
    float scale;
};
struct GemmArgs { GemmJob j[3]; };

constexpr int GM_BUF  = 98304;               // Ah16K Al16K Bh32K Bl32K
constexpr int GM_SMEM = 1024 + 2 * GM_BUF;   // 197632 (< 227KB sm_103a max)

template <int OSPLIT>
__global__ __launch_bounds__(256, 1) void tc_gemm(GemmArgs args)
{
    const GemmJob J = args.j[blockIdx.z];
    extern __shared__ char sm[];
    const u32 sbase = smem_u32(sm);
    const u32 abase = (sbase + 1023) & ~1023u;
    const int tid = threadIdx.x;
    const int m0 = blockIdx.y * 128, n0 = blockIdx.x * 256;

    const __nv_bfloat16* ah_g = J.Ah + (long)m0 * Kn;
    const __nv_bfloat16* al_g = J.Al + (long)m0 * Kn;
    const __nv_bfloat16* bh_g = J.Bh + (long)n0 * Kn;
    const __nv_bfloat16* bl_g = J.Bl + (long)n0 * Kn;

    auto stage = [&](int c, int b) {
        const u32 dst = abase + b * GM_BUF;
        const int koff = c * 64;
        // A hi/lo: 128 rows x 8 quads each
#pragma unroll
        for (int i = 0; i < 4; i++) {
            const int q = tid + i * 256;
            const int row = q >> 3, qd = q & 7;
            const u32 so = row * 128 + ((qd * 16) ^ ((row & 7) << 4));
            cpa16(dst + so,         ah_g + (long)row * Kn + koff + qd * 8);
            cpa16(dst + 16384 + so, al_g + (long)row * Kn + koff + qd * 8);
        }
        // B hi/lo: 256 rows x 8 quads each
#pragma unroll
        for (int i = 0; i < 8; i++) {
            const int q = tid + i * 256;
            const int row = q >> 3, qd = q & 7;
            const u32 so = row * 128 + ((qd * 16) ^ ((row & 7) << 4));
            cpa16(dst + 32768 + so, bh_g + (long)row * Kn + koff + qd * 8);
            cpa16(dst + 65536 + so, bl_g + (long)row * Kn + koff + qd * 8);
        }
    };

    const int lane = tid & 31, wid = tid >> 5;
    const int wm = wid >> 2, wn = wid & 3;
    const int Rr = wm * 64, Ncol = wn * 64;
    const int lrow = (lane & 7) + ((lane >> 3) & 1) * 8;
    const int lkb  = (lane >> 4) * 16;
    const int xorm = (lrow & 7) << 4;

    float acc[4][8][4];
#pragma unroll
    for (int mb = 0; mb < 4; mb++)
#pragma unroll
        for (int nb = 0; nb < 8; nb++)
#pragma unroll
            for (int r = 0; r < 4; r++) acc[mb][nb][r] = 0.f;

    stage(0, 0);
    asm volatile("cp.async.commit_group;" ::: "memory");

    for (int c = 0; c < 16; c++) {
        if (c < 15) {
            stage(c + 1, (c + 1) & 1);
            asm volatile("cp.async.commit_group;" ::: "memory");
            asm volatile("cp.async.wait_group 1;" ::: "memory");
        } else {
            asm volatile("cp.async.wait_group 0;" ::: "memory");
        }
        __syncthreads();

        const u32 sb = abase + (c & 1) * GM_BUF;
        const u32 arow0 = sb + (Rr + lrow) * 128;
        const u32 brow0 = sb + 32768 + (Ncol + lrow) * 128;
#pragma unroll
        for (int t = 0; t < 4; t++) {
            const u32 cb = (u32)((32 * t + lkb) ^ xorm);
            u32 ah[4][4], al[4][4];
#pragma unroll
            for (int mb = 0; mb < 4; mb++) {
                ldsm4(ah[mb], arow0 + mb * 2048 + cb);
                ldsm4(al[mb], arow0 + 16384 + mb * 2048 + cb);
            }
#pragma unroll
            for (int g = 0; g < 4; g++) {
                u32 bh[4], bl[4];
                ldsm4(bh, brow0 + g * 2048 + cb);
                ldsm4(bl, brow0 + 32768 + g * 2048 + cb);
#pragma unroll
                for (int mb = 0; mb < 4; mb++) {
                    mma_bf16(acc[mb][2 * g],     ah[mb], bh[0], bh[2]);
                    mma_bf16(acc[mb][2 * g],     ah[mb], bl[0], bl[2]);
                    mma_bf16(acc[mb][2 * g],     al[mb], bh[0], bh[2]);
                    mma_bf16(acc[mb][2 * g + 1], ah[mb], bh[1], bh[3]);
                    mma_bf16(acc[mb][2 * g + 1], ah[mb], bl[1], bl[3]);
                    mma_bf16(acc[mb][2 * g + 1], al[mb], bh[1], bh[3]);
                }
            }
        }
        __syncthreads();
    }

#pragma unroll
    for (int mb = 0; mb < 4; mb++) {
        const int row = m0 + Rr + 16 * mb + (lane >> 2);
#pragma unroll
        for (int nb = 0; nb < 8; nb++) {
            const int col = n0 + Ncol + nb * 8 + (lane & 3) * 2;
            const float2 bb = *(const float2*)(J.bias + col);
            float v0 = acc[mb][nb][0] + bb.x, v1 = acc[mb][nb][1] + bb.y;
            float v2 = acc[mb][nb][2] + bb.x, v3 = acc[mb][nb][3] + bb.y;
            if (OSPLIT) {
                v0 *= J.scale; v1 *= J.scale; v2 *= J.scale; v3 *= J.scale;
                const u32 hi0 = cvt2(v1, v0);
                const u32 lo0 = cvt2(v1 - bhi(hi0), v0 - blo(hi0));
                const u32 hi1 = cvt2(v3, v2);
                const u32 lo1 = cvt2(v3 - bhi(hi1), v2 - blo(hi1));
                *(u32*)(J.Ch + (long)row * Nn + col)       = hi0;
                *(u32*)(J.Cl + (long)row * Nn + col)       = lo0;
                *(u32*)(J.Ch + (long)(row + 8) * Nn + col) = hi1;
                *(u32*)(J.Cl + (long)(row + 8) * Nn + col) = lo1;
            } else {
                *(float2*)(J.Cf + (long)row * Nn + col)       = make_float2(v0, v1);
                *(float2*)(J.Cf + (long)(row + 8) * Nn + col) = make_float2(v2, v3);
            }
        }
    }
}

// ---------------------------------------------------------------------------
// Tensor-core flash attention (HMMA, split-bf16, base-2 softmax). Unchanged.
// ---------------------------------------------------------------------------
constexpr int FL_SMEM = 99328;   // 1KB align + Qh/Ql 32KB + 2 x 32KB K/V bufs

__global__ __launch_bounds__(256) void flash_tc(
    const __nv_bfloat16* __restrict__ qh_g, const __nv_bfloat16* __restrict__ ql_g,
    const __nv_bfloat16* __restrict__ kh_g, const __nv_bfloat16* __restrict__ kl_g,
    const __nv_bfloat16* __restrict__ vh_g, const __nv_bfloat16* __restrict__ vl_g,
    __nv_bfloat16* __restrict__ aoh, __nv_bfloat16* __restrict__ aol)
{
    extern __shared__ char sm[];
    const u32 sbase = smem_u32(sm);
    const u32 abase = (sbase + 1023) & ~1023u;
    const int tid = threadIdx.x, lane = tid & 31, wid = tid >> 5;
    const int r0 = blockIdx.x * 128;
    const int h  = blockIdx.y;
    const int b  = blockIdx.z;
    const int Rr = wid * 16;

    const long qoff = ((long)(b * SQn + r0)) * Dn + h * HDn;
    const long koff0 = ((long)(b * SKn)) * Dn + h * HDn;

#pragma unroll
    for (int i = 0; i < 4; i++) {
        const int q = tid + i * 256;
        const int row = q >> 3, qd = q & 7;
        const u32 dst = abase + row * 128 + ((qd * 16) ^ ((row & 7) << 4));
        const long g = qoff + (long)row * Dn + qd * 8;
        cpa16(dst, qh_g + g);
        cpa16(dst + 16384, ql_g + g);
    }
    asm volatile("cp.async.commit_group;" ::: "memory");

    auto stageKV = [&](int c, int buf) {
        const u32 dst0 = abase + 32768 + buf * 32768;
        const long koff = koff0 + (long)(c * 64) * Dn;
#pragma unroll
        for (int i = 0; i < 2; i++) {
            const int q = tid + i * 256;
            const int row = q >> 3, qd = q & 7;
            const u32 so = row * 128 + ((qd * 16) ^ ((row & 7) << 4));
            const long g = koff + (long)row * Dn + qd * 8;
            cpa16(dst0 + so,         kh_g + g);
            cpa16(dst0 + 8192 + so,  kl_g + g);
            cpa16(dst0 + 16384 + so, vh_g + g);
            cpa16(dst0 + 24576 + so, vl_g + g);
        }
    };
    stageKV(0, 0);
    asm volatile("cp.async.commit_group;" ::: "memory");
    asm volatile("cp.async.wait_group 1;" ::: "memory");   // Q ready
    __syncthreads();

    const int lrow = (lane & 7) + ((lane >> 3) & 1) * 8;
    const int lkb  = (lane >> 4) * 16;
    u32 qh[4][4], ql[4][4];
#pragma unroll
    for (int t = 0; t < 4; t++) {
        const u32 ad = abase + (Rr + lrow) * 128 +
                       (((u32)(t * 32 + lkb)) ^ ((lrow & 7) << 4));
        ldsm4(qh[t], ad);
        ldsm4(ql[t], ad + 16384);
    }

    float O[8][4];
#pragma unroll
    for (int nb = 0; nb < 8; nb++)
#pragma unroll
        for (int r = 0; r < 4; r++) O[nb][r] = 0.f;
    float m0 = -3.0e38f, m1 = -3.0e38f, l0 = 0.f, l1 = 0.f;

    for (int c = 0; c < 32; c++) {
        if (c < 31) {
            stageKV(c + 1, (c + 1) & 1);
            asm volatile("cp.async.commit_group;" ::: "memory");
            asm volatile("cp.async.wait_group 1;" ::: "memory");
        } else {
            asm volatile("cp.async.wait_group 0;" ::: "memory");
        }
        __syncthreads();

        const u32 kb = abase + 32768 + (c & 1) * 32768;

        float S[8][4];
#pragma unroll
        for (int nb = 0; nb < 8; nb++)
#pragma unroll
            for (int r = 0; r < 4; r++) S[nb][r] = 0.f;

#pragma unroll
        for (int t = 0; t < 4; t++) {
            const u32 cb = (((u32)(t * 32 + lkb)) ^ ((lrow & 7) << 4));
#pragma unroll
            for (int g = 0; g < 4; g++) {
                u32 kh_[4], kl_[4];
                const u32 ad = kb + (g * 16 + lrow) * 128 + cb;
                ldsm4(kh_, ad);
                ldsm4(kl_, ad + 8192);
                mma_bf16(S[2 * g],     qh[t], kh_[0], kh_[2]);
                mma_bf16(S[2 * g],     qh[t], kl_[0], kl_[2]);
                mma_bf16(S[2 * g],     ql[t], kh_[0], kh_[2]);
                mma_bf16(S[2 * g + 1], qh[t], kh_[1], kh_[3]);
                mma_bf16(S[2 * g + 1], qh[t], kl_[1], kl_[3]);
                mma_bf16(S[2 * g + 1], ql[t], kh_[1], kh_[3]);
            }
        }

        float mx0 = -3.0e38f, mx1 = -3.0e38f;
#pragma unroll
        for (int nb = 0; nb < 8; nb++) {
            mx0 = fmaxf(mx0, fmaxf(S[nb][0], S[nb][1]));
            mx1 = fmaxf(mx1, fmaxf(S[nb][2], S[nb][3]));
        }
        mx0 = fmaxf(mx0, __shfl_xor_sync(0xFFFFFFFFu, mx0, 1));
        mx0 = fmaxf(mx0, __shfl_xor_sync(0xFFFFFFFFu, mx0, 2));
        mx1 = fmaxf(mx1, __shfl_xor_sync(0xFFFFFFFFu, mx1, 1));
        mx1 = fmaxf(mx1, __shfl_xor_sync(0xFFFFFFFFu, mx1, 2));
        const float mn0 = fmaxf(m0, mx0), mn1 = fmaxf(m1, mx1);
        const float f0 = exp2f(m0 - mn0), f1 = exp2f(m1 - mn1);
        m0 = mn0; m1 = mn1;
        float s0 = 0.f, s1 = 0.f;
#pragma unroll
        for (int nb = 0; nb < 8; nb++) {
            S[nb][0] = exp2f(S[nb][0] - m0); s0 += S[nb][0];
            S[nb][1] = exp2f(S[nb][1] - m0); s0 += S[nb][1];
            S[nb][2] = exp2f(S[nb][2] - m1); s1 += S[nb][2];
            S[nb][3] = exp2f(S[nb][3] - m1); s1 += S[nb][3];
        }
        s0 += __shfl_xor_sync(0xFFFFFFFFu, s0, 1);
        s0 += __shfl_xor_sync(0xFFFFFFFFu, s0, 2);
        s1 += __shfl_xor_sync(0xFFFFFFFFu, s1, 1);
        s1 += __shfl_xor_sync(0xFFFFFFFFu, s1, 2);
        l0 = l0 * f0 + s0;
        l1 = l1 * f1 + s1;
#pragma unroll
        for (int nb = 0; nb < 8; nb++) {
            O[nb][0] *= f0; O[nb][1] *= f0;
            O[nb][2] *= f1; O[nb][3] *= f1;
        }

        const u32 vb = kb + 16384;
        const int vkey0 = ((lane >> 3) & 1) * 8 + (lane & 7);
        const int vcolb = (lane >> 4) * 16;
#pragma unroll
        for (int t = 0; t < 4; t++) {
            u32 ph[4], pl[4];
            ph[0] = cvt2(S[2 * t][1],     S[2 * t][0]);
            ph[1] = cvt2(S[2 * t][3],     S[2 * t][2]);
            ph[2] = cvt2(S[2 * t + 1][1], S[2 * t + 1][0]);
            ph[3] = cvt2(S[2 * t + 1][3], S[2 * t + 1][2]);
            pl[0] = cvt2(S[2 * t][1] - bhi(ph[0]),     S[2 * t][0] - blo(ph[0]));
            pl[1] = cvt2(S[2 * t][3] - bhi(ph[1]),     S[2 * t][2] - blo(ph[1]));
            pl[2] = cvt2(S[2 * t + 1][1] - bhi(ph[2]), S[2 * t + 1][0] - blo(ph[2]));
            pl[3] = cvt2(S[2 * t + 1][3] - bhi(ph[3]), S[2 * t + 1][2] - blo(ph[3]));

            const int vkey = t * 16 + vkey0;
            const u32 vrow = vb + vkey * 128;
            const u32 vxor = (vkey & 7) << 4;
#pragma unroll
            for (int np = 0; np < 4; np++) {
                u32 vh_[4], vl_[4];
                const u32 ad = vrow + (((u32)(np * 32 + vcolb)) ^ vxor);
                ldsm4t(vh_, ad);
                ldsm4t(vl_, ad + 8192);
                mma_bf16(O[2 * np],     ph, vh_[0], vh_[1]);
                mma_bf16(O[2 * np],     ph, vl_[0], vl_[1]);
                mma_bf16(O[2 * np],     pl, vh_[0], vh_[1]);
                mma_bf16(O[2 * np + 1], ph, vh_[2], vh_[3]);
                mma_bf16(O[2 * np + 1], ph, vl_[2], vl_[3]);
                mma_bf16(O[2 * np + 1], pl, vh_[2], vh_[3]);
            }
        }
        __syncthreads();
    }

    const float inv0 = 1.f / l0, inv1 = 1.f / l1;
    const int row = r0 + Rr + (lane >> 2);
    const long ob0 = ((long)(b * SQn + row)) * Dn + h * HDn + 2 * (lane & 3);
    const long ob1 = ob0 + 8 * Dn;
#pragma unroll
    for (int nb = 0; nb < 8; nb++) {
        const float o0 = O[nb][0] * inv0, o1 = O[nb][1] * inv0;
        const float o2 = O[nb][2] * inv1, o3 = O[nb][3] * inv1;
        const u32 hi0 = cvt2(o1, o0);
        const u32 lo0 = cvt2(o1 - bhi(hi0), o0 - blo(hi0));
        const u32 hi1 = cvt2(o3, o2);
        const u32 lo1 = cvt2(o3 - bhi(hi1), o2 - blo(hi1));
        *(u32*)(aoh + ob0 + nb * 8) = hi0;
        *(u32*)(aol + ob0 + nb * 8) = lo0;
        *(u32*)(aoh + ob1 + nb * 8) = hi1;
        *(u32*)(aol + ob1 + nb * 8) = lo1;
    }
}

// ---------------------------------------------------------------------------
extern "C" void kernel_launch(void* const* d_in, const int* in_sizes, int n_in,
                              void* d_out, int out_size)
{
    const float* x   = (const float*)d_in[0];
    const float* enc = (const float*)d_in[1];
    const float* Wq  = (const float*)d_in[2];
    const float* bq  = (const float*)d_in[3];
    const float* Wk  = (const float*)d_in[4];
    const float* bk  = (const float*)d_in[5];
    const float* Wv  = (const float*)d_in[6];
    const float* bv  = (const float*)d_in[7];
    const float* Wo  = (const float*)d_in[8];
    const float* bo  = (const float*)d_in[9];
    float* out = (float*)d_out;

    __nv_bfloat16 (*wh)[Nn * Kn]; __nv_bfloat16 (*wl)[Nn * Kn];
    __nv_bfloat16 (*ah)[Mn * Dn]; __nv_bfloat16 (*al)[Mn * Dn];
    __nv_bfloat16 *qh, *ql, *kh, *kl, *vh, *vl, *aoh, *aol;
    cudaGetSymbolAddress((void**)&wh, g_wh);
    cudaGetSymbolAddress((void**)&wl, g_wl);
    cudaGetSymbolAddress((void**)&ah, g_ah);
    cudaGetSymbolAddress((void**)&al, g_al);
    cudaGetSymbolAddress((void**)&qh, g_qh);
    cudaGetSymbolAddress((void**)&ql, g_ql);
    cudaGetSymbolAddress((void**)&kh, g_kh);
    cudaGetSymbolAddress((void**)&kl, g_kl);
    cudaGetSymbolAddress((void**)&vh, g_vh);
    cudaGetSymbolAddress((void**)&vl, g_vl);
    cudaGetSymbolAddress((void**)&aoh, g_aoh);
    cudaGetSymbolAddress((void**)&aol, g_aol);

    cudaFuncSetAttribute(tc_gemm<0>,
                         cudaFuncAttributeMaxDynamicSharedMemorySize, GM_SMEM);
    cudaFuncSetAttribute(tc_gemm<1>,
                         cudaFuncAttributeMaxDynamicSharedMemorySize, GM_SMEM);
    cudaFuncSetAttribute(flash_tc,
                         cudaFuncAttributeMaxDynamicSharedMemorySize, FL_SMEM);

    // Pre-passes (merged)
    wsplit_all<<<dim3(16, 16, 4), 256>>>(Wq, Wk, Wv, Wo, wh[0], wl[0]);
    asplit_all<<<8192, 256>>>(x, enc, ah[0], al[0]);

    const float qscale = 0.125f * 1.44269504088896f;   // 1/sqrt(HD) * log2(e)

    // QKV projections: one fused launch, gridDim.z = 3
    GemmArgs qkv;
    qkv.j[0] = { ah[0], al[0], wh[0], wl[0], bq, nullptr, qh, ql, qscale };
    qkv.j[1] = { ah[1], al[1], wh[1], wl[1], bk, nullptr, kh, kl, 1.0f };
    qkv.j[2] = { ah[1], al[1], wh[2], wl[2], bv, nullptr, vh, vl, 1.0f };
    tc_gemm<1><<<dim3(Nn / 256, Mn / 128, 3), 256, GM_SMEM>>>(qkv);

    flash_tc<<<dim3(SQn / 128, Hn, Bb), 256, FL_SMEM>>>(qh, ql, kh, kl, vh, vl,
                                                        aoh, aol);

    // Output projection
    GemmArgs og;
    og.j[0] = { aoh, aol, wh[3], wl[3], bo, out, nullptr, nullptr, 1.0f };
    og.j[1] = og.j[0];
    og.j[2] = og.j[0];
    tc_gemm<0><<<dim3(Nn / 256, Mn / 128, 1), 256, GM_SMEM>>>(og);
}

// round 15
// speedup vs baseline: 8.7044x; 1.0943x over previous
#include <cuda_runtime.h>
#include <cuda_bf16.h>

typedef unsigned long long u64;
typedef unsigned int u32;

// Problem dims (fixed by the reference)
constexpr int Bb  = 2;
constexpr int SQn = 2048;
constexpr int SKn = 2048;
constexpr int Dn  = 1024;
constexpr int Hn  = 16;
constexpr int HDn = 64;

constexpr int Mn = Bb * SQn;   // 4096
constexpr int Nn = 1024;
constexpr int Kn = 1024;

// Scratch (static device globals; no dynamic allocation allowed)
__device__ __nv_bfloat16 g_wh[4][Nn * Kn];    // transposed weights, hi
__device__ __nv_bfloat16 g_wl[4][Nn * Kn];    // transposed weights, lo
__device__ __nv_bfloat16 g_ah[2][Mn * Dn];    // activations hi: x, enc
__device__ __nv_bfloat16 g_al[2][Mn * Dn];    // activations lo
__device__ __nv_bfloat16 g_qh[Mn * Dn], g_ql[Mn * Dn];   // q hi/lo (pre-scaled)
__device__ __nv_bfloat16 g_kh[Mn * Dn], g_kl[Mn * Dn];
__device__ __nv_bfloat16 g_vh[Mn * Dn], g_vl[Mn * Dn];
__device__ __nv_bfloat16 g_aoh[Mn * Dn], g_aol[Mn * Dn]; // attention out hi/lo

// ============================ PTX helpers ===================================
__device__ __forceinline__ u32 smem_u32(const void* p) {
    u32 a;
    asm("{ .reg .u64 t; cvta.to.shared.u64 t, %1; cvt.u32.u64 %0, t; }"
        : "=r"(a) : "l"(p));
    return a;
}
__device__ __forceinline__ void ldsm4(u32* r, u32 addr) {
    asm volatile("ldmatrix.sync.aligned.m8n8.x4.shared.b16 {%0,%1,%2,%3}, [%4];"
                 : "=r"(r[0]), "=r"(r[1]), "=r"(r[2]), "=r"(r[3]) : "r"(addr));
}
__device__ __forceinline__ void ldsm4t(u32* r, u32 addr) {
    asm volatile("ldmatrix.sync.aligned.m8n8.x4.trans.shared.b16 {%0,%1,%2,%3}, [%4];"
                 : "=r"(r[0]), "=r"(r[1]), "=r"(r[2]), "=r"(r[3]) : "r"(addr));
}
__device__ __forceinline__ void mma_bf16(float* d, const u32* a, u32 b0, u32 b1) {
    asm volatile("mma.sync.aligned.m16n8k16.row.col.f32.bf16.bf16.f32 "
                 "{%0,%1,%2,%3}, {%4,%5,%6,%7}, {%8,%9}, {%0,%1,%2,%3};"
                 : "+f"(d[0]), "+f"(d[1]), "+f"(d[2]), "+f"(d[3])
                 : "r"(a[0]), "r"(a[1]), "r"(a[2]), "r"(a[3]), "r"(b0), "r"(b1));
}
__device__ __forceinline__ void cpa16(u32 saddr, const void* g) {
    asm volatile("cp.async.cg.shared.global [%0], [%1], 16;"
                 :: "r"(saddr), "l"(g) : "memory");
}
// pack two fp32 -> bf16x2 (hi goes to upper 16 bits)
__device__ __forceinline__ u32 cvt2(float hi, float lo) {
    u32 d;
    asm("cvt.rn.bf16x2.f32 %0, %1, %2;" : "=r"(d) : "f"(hi), "f"(lo));
    return d;
}
__device__ __forceinline__ float blo(u32 r) { return __uint_as_float(r << 16); }
__device__ __forceinline__ float bhi(u32 r) { return __uint_as_float(r & 0xFFFF0000u); }

// ---------------------------------------------------------------------------
// Weight pre-pass (merged): z = 0..2 -> Wq/Wk/Wv ([H,D,HD]); z = 3 -> Wo ([K,N]).
// Transpose to Wt[n][k] and split fp32 -> bf16 hi + lo.
// ---------------------------------------------------------------------------
__global__ __launch_bounds__(256) void wsplit_all(
    const float* __restrict__ W0, const float* __restrict__ W1,
    const float* __restrict__ W2, const float* __restrict__ W3,
    __nv_bfloat16* __restrict__ Th0, __nv_bfloat16* __restrict__ Tl0)
{
    __shared__ float tile[64][65];
    const int z  = blockIdx.z;
    const float* W = (z == 0) ? W0 : (z == 1) ? W1 : (z == 2) ? W2 : W3;
    __nv_bfloat16* Th = Th0 + (long)z * Nn * Kn;
    __nv_bfloat16* Tl = Tl0 + (long)z * Nn * Kn;
    const int k0 = blockIdx.x * 64;
    const int by = blockIdx.y;
    const int tid = threadIdx.x;
#pragma unroll
    for (int i = 0; i < 16; i++) {
        const int idx = tid + i * 256;
        const int kk = idx >> 6, e = idx & 63;
        long off;
        if (z < 3) off = (long)by * 65536 + (long)(k0 + kk) * 64 + e;
        else       off = (long)(k0 + kk) * Nn + by * 64 + e;
        tile[kk][e] = W[off];
    }
    __syncthreads();
#pragma unroll
    for (int i = 0; i < 16; i++) {
        const int idx = tid + i * 256;
        const int e = idx >> 6, kk = idx & 63;
        const float v = tile[kk][e];
        const __nv_bfloat16 h = __float2bfloat16(v);
        const __nv_bfloat16 l = __float2bfloat16(v - __bfloat162float(h));
        const long o = (long)(by * 64 + e) * Kn + k0 + kk;
        Th[o] = h;
        Tl[o] = l;
    }
}

// ---------------------------------------------------------------------------
// Activation split (merged x + enc): 8192 blocks; first 4096 -> x, rest -> enc.
// ---------------------------------------------------------------------------
__global__ __launch_bounds__(256) void asplit_all(
    const float* __restrict__ x, const float* __restrict__ enc,
    __nv_bfloat16* __restrict__ h0, __nv_bfloat16* __restrict__ l0)
{
    const int z = (blockIdx.x >= 4096) ? 1 : 0;
    const float* in = z ? enc : x;
    __nv_bfloat16* h = h0 + (long)z * Mn * Dn;
    __nv_bfloat16* l = l0 + (long)z * Mn * Dn;
    const long i = ((long)(blockIdx.x - z * 4096) * 256 + threadIdx.x) * 4;
    const float4 t = *(const float4*)(in + i);
    const u32 p0 = cvt2(t.y, t.x);
    const u32 p1 = cvt2(t.w, t.z);
    const u32 q0 = cvt2(t.y - bhi(p0), t.x - blo(p0));
    const u32 q1 = cvt2(t.w - bhi(p1), t.z - blo(p1));
    *(uint2*)(h + i) = make_uint2(p0, p1);
    *(uint2*)(l + i) = make_uint2(q0, q1);
}

// ---------------------------------------------------------------------------
// Tensor-core split-bf16 GEMM (HMMA): C = A * Wt^T + bias
// CTA tile 128x256, BK=64, 8 warps as 2m x 4n, warp tile 64x64.
// gridDim.z selects a GemmJob (QKV fused in one launch).
// OSPLIT=0: C fp32 row-major.  OSPLIT=1: C as bf16 hi/lo pair arrays * scale.
// ---------------------------------------------------------------------------
struct GemmJob {
    const __nv_bfloat16 *Ah, *Al, *Bh, *Bl;
    const float* bias;
    float* Cf;
    __nv_bfloat16 *Ch, *Cl;
    float scale;
};
struct GemmArgs { GemmJob j[3]; };

constexpr int GM_BUF  = 98304;               // Ah16K Al16K Bh32K Bl32K
constexpr int GM_SMEM = 1024 + 2 * GM_BUF;   // 197632

template <int OSPLIT>
__global__ __launch_bounds__(256, 1) void tc_gemm(GemmArgs args)
{
    const GemmJob J = args.j[blockIdx.z];
    extern __shared__ char sm[];
    const u32 sbase = smem_u32(sm);
    const u32 abase = (sbase + 1023) & ~1023u;
    const int tid = threadIdx.x;
    const int m0 = blockIdx.y * 128, n0 = blockIdx.x * 256;

    const __nv_bfloat16* ah_g = J.Ah + (long)m0 * Kn;
    const __nv_bfloat16* al_g = J.Al + (long)m0 * Kn;
    const __nv_bfloat16* bh_g = J.Bh + (long)n0 * Kn;
    const __nv_bfloat16* bl_g = J.Bl + (long)n0 * Kn;

    auto stage = [&](int c, int b) {
        const u32 dst = abase + b * GM_BUF;
        const int koff = c * 64;
#pragma unroll
        for (int i = 0; i < 4; i++) {
            const int q = tid + i * 256;
            const int row = q >> 3, qd = q & 7;
            const u32 so = row * 128 + ((qd * 16) ^ ((row & 7) << 4));
            cpa16(dst + so,         ah_g + (long)row * Kn + koff + qd * 8);
            cpa16(dst + 16384 + so, al_g + (long)row * Kn + koff + qd * 8);
        }
#pragma unroll
        for (int i = 0; i < 8; i++) {
            const int q = tid + i * 256;
            const int row = q >> 3, qd = q & 7;
            const u32 so = row * 128 + ((qd * 16) ^ ((row & 7) << 4));
            cpa16(dst + 32768 + so, bh_g + (long)row * Kn + koff + qd * 8);
            cpa16(dst + 65536 + so, bl_g + (long)row * Kn + koff + qd * 8);
        }
    };

    const int lane = tid & 31, wid = tid >> 5;
    const int wm = wid >> 2, wn = wid & 3;
    const int Rr = wm * 64, Ncol = wn * 64;
    const int lrow = (lane & 7) + ((lane >> 3) & 1) * 8;
    const int lkb  = (lane >> 4) * 16;
    const int xorm = (lrow & 7) << 4;

    float acc[4][8][4];
#pragma unroll
    for (int mb = 0; mb < 4; mb++)
#pragma unroll
        for (int nb = 0; nb < 8; nb++)
#pragma unroll
            for (int r = 0; r < 4; r++) acc[mb][nb][r] = 0.f;

    stage(0, 0);
    asm volatile("cp.async.commit_group;" ::: "memory");

    for (int c = 0; c < 16; c++) {
        if (c < 15) {
            stage(c + 1, (c + 1) & 1);
            asm volatile("cp.async.commit_group;" ::: "memory");
            asm volatile("cp.async.wait_group 1;" ::: "memory");
        } else {
            asm volatile("cp.async.wait_group 0;" ::: "memory");
        }
        __syncthreads();

        const u32 sb = abase + (c & 1) * GM_BUF;
        const u32 arow0 = sb + (Rr + lrow) * 128;
        const u32 brow0 = sb + 32768 + (Ncol + lrow) * 128;
#pragma unroll
        for (int t = 0; t < 4; t++) {
            const u32 cb = (u32)((32 * t + lkb) ^ xorm);
            u32 ah[4][4], al[4][4];
#pragma unroll
            for (int mb = 0; mb < 4; mb++) {
                ldsm4(ah[mb], arow0 + mb * 2048 + cb);
                ldsm4(al[mb], arow0 + 16384 + mb * 2048 + cb);
            }
#pragma unroll
            for (int g = 0; g < 4; g++) {
                u32 bh[4], bl[4];
                ldsm4(bh, brow0 + g * 2048 + cb);
                ldsm4(bl, brow0 + 32768 + g * 2048 + cb);
#pragma unroll
                for (int mb = 0; mb < 4; mb++) {
                    mma_bf16(acc[mb][2 * g],     ah[mb], bh[0], bh[2]);
                    mma_bf16(acc[mb][2 * g],     ah[mb], bl[0], bl[2]);
                    mma_bf16(acc[mb][2 * g],     al[mb], bh[0], bh[2]);
                    mma_bf16(acc[mb][2 * g + 1], ah[mb], bh[1], bh[3]);
                    mma_bf16(acc[mb][2 * g + 1], ah[mb], bl[1], bl[3]);
                    mma_bf16(acc[mb][2 * g + 1], al[mb], bh[1], bh[3]);
                }
            }
        }
        __syncthreads();
    }

#pragma unroll
    for (int mb = 0; mb < 4; mb++) {
        const int row = m0 + Rr + 16 * mb + (lane >> 2);
#pragma unroll
        for (int nb = 0; nb < 8; nb++) {
            const int col = n0 + Ncol + nb * 8 + (lane & 3) * 2;
            const float2 bb = *(const float2*)(J.bias + col);
            float v0 = acc[mb][nb][0] + bb.x, v1 = acc[mb][nb][1] + bb.y;
            float v2 = acc[mb][nb][2] + bb.x, v3 = acc[mb][nb][3] + bb.y;
            if (OSPLIT) {
                v0 *= J.scale; v1 *= J.scale; v2 *= J.scale; v3 *= J.scale;
                const u32 hi0 = cvt2(v1, v0);
                const u32 lo0 = cvt2(v1 - bhi(hi0), v0 - blo(hi0));
                const u32 hi1 = cvt2(v3, v2);
                const u32 lo1 = cvt2(v3 - bhi(hi1), v2 - blo(hi1));
                *(u32*)(J.Ch + (long)row * Nn + col)       = hi0;
                *(u32*)(J.Cl + (long)row * Nn + col)       = lo0;
                *(u32*)(J.Ch + (long)(row + 8) * Nn + col) = hi1;
                *(u32*)(J.Cl + (long)(row + 8) * Nn + col) = lo1;
            } else {
                *(float2*)(J.Cf + (long)row * Nn + col)       = make_float2(v0, v1);
                *(float2*)(J.Cf + (long)(row + 8) * Nn + col) = make_float2(v2, v3);
            }
        }
    }
}

// ---------------------------------------------------------------------------
// Tensor-core flash attention (HMMA, split-bf16, base-2 softmax).
// NEW: CTA = 64 q-rows, 128 threads (4 warps x 16 rows) -> 21K regs/CTA ->
// 3 CTAs/SM (reg-bound before; occ 12.5% -> ~19%). Q is staged through KV
// buffer 0 and then lives in registers; smem = 1KB + 2 x 32KB KV buffers.
// Per-warp tiling and numerics identical to the 256-thread version.
// ---------------------------------------------------------------------------
constexpr int FL_SMEM = 1024 + 2 * 32768;   // 66560

__global__ __launch_bounds__(128, 3) void flash_tc(
    const __nv_bfloat16* __restrict__ qh_g, const __nv_bfloat16* __restrict__ ql_g,
    const __nv_bfloat16* __restrict__ kh_g, const __nv_bfloat16* __restrict__ kl_g,
    const __nv_bfloat16* __restrict__ vh_g, const __nv_bfloat16* __restrict__ vl_g,
    __nv_bfloat16* __restrict__ aoh, __nv_bfloat16* __restrict__ aol)
{
    extern __shared__ char sm[];
    const u32 sbase = smem_u32(sm);
    const u32 abase = (sbase + 1023) & ~1023u;
    const int tid = threadIdx.x, lane = tid & 31, wid = tid >> 5;
    const int r0 = blockIdx.x * 64;
    const int h  = blockIdx.y;
    const int b  = blockIdx.z;
    const int Rr = wid * 16;

    const long qoff  = ((long)(b * SQn + r0)) * Dn + h * HDn;
    const long koff0 = ((long)(b * SKn)) * Dn + h * HDn;

    // Stage Q hi/lo into buffer 0 (8KB + 8KB); it is consumed into registers
    // before buffer 0 is reused for KV tile 1.
#pragma unroll
    for (int i = 0; i < 4; i++) {
        const int q = tid + i * 128;              // 512 quads per array
        const int row = q >> 3, qd = q & 7;       // row 0..63
        const u32 so = row * 128 + ((qd * 16) ^ ((row & 7) << 4));
        const long g = qoff + (long)row * Dn + qd * 8;
        cpa16(abase + so,        qh_g + g);
        cpa16(abase + 8192 + so, ql_g + g);
    }
    asm volatile("cp.async.commit_group;" ::: "memory");

    // KV buffers: buf0 @ abase, buf1 @ abase+32768; layout kh/kl/vh/vl @ +8KB each
    auto stageKV = [&](int c, int buf) {
        const u32 dst0 = abase + buf * 32768;
        const long koff = koff0 + (long)(c * 64) * Dn;
#pragma unroll
        for (int i = 0; i < 4; i++) {
            const int q = tid + i * 128;
            const int row = q >> 3, qd = q & 7;
            const u32 so = row * 128 + ((qd * 16) ^ ((row & 7) << 4));
            const long g = koff + (long)row * Dn + qd * 8;
            cpa16(dst0 + so,         kh_g + g);
            cpa16(dst0 + 8192 + so,  kl_g + g);
            cpa16(dst0 + 16384 + so, vh_g + g);
            cpa16(dst0 + 24576 + so, vl_g + g);
        }
    };
    stageKV(0, 1);                                 // KV tile 0 -> buf1
    asm volatile("cp.async.commit_group;" ::: "memory");
    asm volatile("cp.async.wait_group 1;" ::: "memory");   // Q complete
    __syncthreads();

    const int lrow = (lane & 7) + ((lane >> 3) & 1) * 8;
    const int lkb  = (lane >> 4) * 16;
    u32 qh[4][4], ql[4][4];
#pragma unroll
    for (int t = 0; t < 4; t++) {
        const u32 ad = abase + (Rr + lrow) * 128 +
                       (((u32)(t * 32 + lkb)) ^ ((lrow & 7) << 4));
        ldsm4(qh[t], ad);
        ldsm4(ql[t], ad + 8192);
    }
    __syncthreads();   // all warps hold Q frags; buffer 0 is now free

    float O[8][4];
#pragma unroll
    for (int nb = 0; nb < 8; nb++)
#pragma unroll
        for (int r = 0; r < 4; r++) O[nb][r] = 0.f;
    float m0 = -3.0e38f, m1 = -3.0e38f, l0 = 0.f, l1 = 0.f;

    for (int c = 0; c < 32; c++) {
        if (c < 31) {
            stageKV(c + 1, c & 1);   // KV1->buf0, KV2->buf1, ...
            asm volatile("cp.async.commit_group;" ::: "memory");
            asm volatile("cp.async.wait_group 1;" ::: "memory");   // KV_c done
        } else {
            asm volatile("cp.async.wait_group 0;" ::: "memory");
        }
        __syncthreads();

        const u32 kb = abase + ((c + 1) & 1) * 32768;   // KV_c: even->buf1, odd->buf0

        float S[8][4];
#pragma unroll
        for (int nb = 0; nb < 8; nb++)
#pragma unroll
            for (int r = 0; r < 4; r++) S[nb][r] = 0.f;

#pragma unroll
        for (int t = 0; t < 4; t++) {
            const u32 cb = (((u32)(t * 32 + lkb)) ^ ((lrow & 7) << 4));
#pragma unroll
            for (int g = 0; g < 4; g++) {
                u32 kh_[4], kl_[4];
                const u32 ad = kb + (g * 16 + lrow) * 128 + cb;
                ldsm4(kh_, ad);
                ldsm4(kl_, ad + 8192);
                mma_bf16(S[2 * g],     qh[t], kh_[0], kh_[2]);
                mma_bf16(S[2 * g],     qh[t], kl_[0], kl_[2]);
                mma_bf16(S[2 * g],     ql[t], kh_[0], kh_[2]);
                mma_bf16(S[2 * g + 1], qh[t], kh_[1], kh_[3]);
                mma_bf16(S[2 * g + 1], qh[t], kl_[1], kl_[3]);
                mma_bf16(S[2 * g + 1], ql[t], kh_[1], kh_[3]);
            }
        }

        float mx0 = -3.0e38f, mx1 = -3.0e38f;
#pragma unroll
        for (int nb = 0; nb < 8; nb++) {
            mx0 = fmaxf(mx0, fmaxf(S[nb][0], S[nb][1]));
            mx1 = fmaxf(mx1, fmaxf(S[nb][2], S[nb][3]));
        }
        mx0 = fmaxf(mx0, __shfl_xor_sync(0xFFFFFFFFu, mx0, 1));
        mx0 = fmaxf(mx0, __shfl_xor_sync(0xFFFFFFFFu, mx0, 2));
        mx1 = fmaxf(mx1, __shfl_xor_sync(0xFFFFFFFFu, mx1, 1));
        mx1 = fmaxf(mx1, __shfl_xor_sync(0xFFFFFFFFu, mx1, 2));
        const float mn0 = fmaxf(m0, mx0), mn1 = fmaxf(m1, mx1);
        const float f0 = exp2f(m0 - mn0), f1 = exp2f(m1 - mn1);
        m0 = mn0; m1 = mn1;
        float s0 = 0.f, s1 = 0.f;
#pragma unroll
        for (int nb = 0; nb < 8; nb++) {
            S[nb][0] = exp2f(S[nb][0] - m0); s0 += S[nb][0];
            S[nb][1] = exp2f(S[nb][1] - m0); s0 += S[nb][1];
            S[nb][2] = exp2f(S[nb][2] - m1); s1 += S[nb][2];
            S[nb][3] = exp2f(S[nb][3] - m1); s1 += S[nb][3];
        }
        s0 += __shfl_xor_sync(0xFFFFFFFFu, s0, 1);
        s0 += __shfl_xor_sync(0xFFFFFFFFu, s0, 2);
        s1 += __shfl_xor_sync(0xFFFFFFFFu, s1, 1);
        s1 += __shfl_xor_sync(0xFFFFFFFFu, s1, 2);
        l0 = l0 * f0 + s0;
        l1 = l1 * f1 + s1;
#pragma unroll
        for (int nb = 0; nb < 8; nb++) {
            O[nb][0] *= f0; O[nb][1] *= f0;
            O[nb][2] *= f1; O[nb][3] *= f1;
        }

        const u32 vb = kb + 16384;
        const int vkey0 = ((lane >> 3) & 1) * 8 + (lane & 7);
        const int vcolb = (lane >> 4) * 16;
#pragma unroll
        for (int t = 0; t < 4; t++) {
            u32 ph[4], pl[4];
            ph[0] = cvt2(S[2 * t][1],     S[2 * t][0]);
            ph[1] = cvt2(S[2 * t][3],     S[2 * t][2]);
            ph[2] = cvt2(S[2 * t + 1][1], S[2 * t + 1][0]);
            ph[3] = cvt2(S[2 * t + 1][3], S[2 * t + 1][2]);
            pl[0] = cvt2(S[2 * t][1] - bhi(ph[0]),     S[2 * t][0] - blo(ph[0]));
            pl[1] = cvt2(S[2 * t][3] - bhi(ph[1]),     S[2 * t][2] - blo(ph[1]));
            pl[2] = cvt2(S[2 * t + 1][1] - bhi(ph[2]), S[2 * t + 1][0] - blo(ph[2]));
            pl[3] = cvt2(S[2 * t + 1][3] - bhi(ph[3]), S[2 * t + 1][2] - blo(ph[3]));

            const int vkey = t * 16 + vkey0;
            const u32 vrow = vb + vkey * 128;
            const u32 vxor = (vkey & 7) << 4;
#pragma unroll
            for (int np = 0; np < 4; np++) {
                u32 vh_[4], vl_[4];
                const u32 ad = vrow + (((u32)(np * 32 + vcolb)) ^ vxor);
                ldsm4t(vh_, ad);
                ldsm4t(vl_, ad + 8192);
                mma_bf16(O[2 * np],     ph, vh_[0], vh_[1]);
                mma_bf16(O[2 * np],     ph, vl_[0], vl_[1]);
                mma_bf16(O[2 * np],     pl, vh_[0], vh_[1]);
                mma_bf16(O[2 * np + 1], ph, vh_[2], vh_[3]);
                mma_bf16(O[2 * np + 1], ph, vl_[2], vl_[3]);
                mma_bf16(O[2 * np + 1], pl, vh_[2], vh_[3]);
            }
        }
        __syncthreads();
    }

    const float inv0 = 1.f / l0, inv1 = 1.f / l1;
    const int row = r0 + Rr + (lane >> 2);
    const long ob0 = ((long)(b * SQn + row)) * Dn + h * HDn + 2 * (lane & 3);
    const long ob1 = ob0 + 8 * Dn;
#pragma unroll
    for (int nb = 0; nb < 8; nb++) {
        const float o0 = O[nb][0] * inv0, o1 = O[nb][1] * inv0;
        const float o2 = O[nb][2] * inv1, o3 = O[nb][3] * inv1;
        const u32 hi0 = cvt2(o1, o0);
        const u32 lo0 = cvt2(o1 - bhi(hi0), o0 - blo(hi0));
        const u32 hi1 = cvt2(o3, o2);
        const u32 lo1 = cvt2(o3 - bhi(hi1), o2 - blo(hi1));
        *(u32*)(aoh + ob0 + nb * 8) = hi0;
        *(u32*)(aol + ob0 + nb * 8) = lo0;
        *(u32*)(aoh + ob1 + nb * 8) = hi1;
        *(u32*)(aol + ob1 + nb * 8) = lo1;
    }
}

// ---------------------------------------------------------------------------
extern "C" void kernel_launch(void* const* d_in, const int* in_sizes, int n_in,
                              void* d_out, int out_size)
{
    const float* x   = (const float*)d_in[0];
    const float* enc = (const float*)d_in[1];
    const float* Wq  = (const float*)d_in[2];
    const float* bq  = (const float*)d_in[3];
    const float* Wk  = (const float*)d_in[4];
    const float* bk  = (const float*)d_in[5];
    const float* Wv  = (const float*)d_in[6];
    const float* bv  = (const float*)d_in[7];
    const float* Wo  = (const float*)d_in[8];
    const float* bo  = (const float*)d_in[9];
    float* out = (float*)d_out;

    __nv_bfloat16 (*wh)[Nn * Kn]; __nv_bfloat16 (*wl)[Nn * Kn];
    __nv_bfloat16 (*ah)[Mn * Dn]; __nv_bfloat16 (*al)[Mn * Dn];
    __nv_bfloat16 *qh, *ql, *kh, *kl, *vh, *vl, *aoh, *aol;
    cudaGetSymbolAddress((void**)&wh, g_wh);
    cudaGetSymbolAddress((void**)&wl, g_wl);
    cudaGetSymbolAddress((void**)&ah, g_ah);
    cudaGetSymbolAddress((void**)&al, g_al);
    cudaGetSymbolAddress((void**)&qh, g_qh);
    cudaGetSymbolAddress((void**)&ql, g_ql);
    cudaGetSymbolAddress((void**)&kh, g_kh);
    cudaGetSymbolAddress((void**)&kl, g_kl);
    cudaGetSymbolAddress((void**)&vh, g_vh);
    cudaGetSymbolAddress((void**)&vl, g_vl);
    cudaGetSymbolAddress((void**)&aoh, g_aoh);
    cudaGetSymbolAddress((void**)&aol, g_aol);

    cudaFuncSetAttribute(tc_gemm<0>,
                         cudaFuncAttributeMaxDynamicSharedMemorySize, GM_SMEM);
    cudaFuncSetAttribute(tc_gemm<1>,
                         cudaFuncAttributeMaxDynamicSharedMemorySize, GM_SMEM);
    cudaFuncSetAttribute(flash_tc,
                         cudaFuncAttributeMaxDynamicSharedMemorySize, FL_SMEM);

    // Pre-passes (merged)
    wsplit_all<<<dim3(16, 16, 4), 256>>>(Wq, Wk, Wv, Wo, wh[0], wl[0]);
    asplit_all<<<8192, 256>>>(x, enc, ah[0], al[0]);

    const float qscale = 0.125f * 1.44269504088896f;   // 1/sqrt(HD) * log2(e)

    // QKV projections: one fused launch, gridDim.z = 3
    GemmArgs qkv;
    qkv.j[0] = { ah[0], al[0], wh[0], wl[0], bq, nullptr, qh, ql, qscale };
    qkv.j[1] = { ah[1], al[1], wh[1], wl[1], bk, nullptr, kh, kl, 1.0f };
    qkv.j[2] = { ah[1], al[1], wh[2], wl[2], bv, nullptr, vh, vl, 1.0f };
    tc_gemm<1><<<dim3(Nn / 256, Mn / 128, 3), 256, GM_SMEM>>>(qkv);

    flash_tc<<<dim3(SQn / 64, Hn, Bb), 128, FL_SMEM>>>(qh, ql, kh, kl, vh, vl,
                                                       aoh, aol);

    // Output projection
    GemmArgs og;
    og.j[0] = { aoh, aol, wh[3], wl[3], bo, out, nullptr, nullptr, 1.0f };
    og.j[1] = og.j[0];
    og.j[2] = og.j[0];
    tc_gemm<0><<<dim3(Nn / 256, Mn / 128, 1), 256, GM_SMEM>>>(og);
}